// round 7
// baseline (speedup 1.0000x reference)
#include <cuda_runtime.h>
#include <math.h>
#include <stdint.h>

#define TOK    4096
#define DMODEL 768
#define NSEQ   512
#define NHEAD  8
#define DHEAD  96
#define NFEAT  256
#define NBH    64
#define NFF    3072
#define NDEPTH 6

// ---------------- scratch ----------------
__device__ float g_x[TOK*DMODEL];
__device__ float g_lnbuf[TOK*DMODEL];
__device__ float g_qkv[TOK*3*DMODEL];
__device__ float g_ffbuf[TOK*NFF];
__device__ float g_uq[NBH*NSEQ*NFEAT];      // raw u_q
__device__ float g_uk[NBH*NSEQ*NFEAT];      // raw u_k
__device__ float g_ctxb[NBH*DHEAD*NFEAT];   // ctxT [bh][96e][256m]
__device__ float g_attn[TOK*DMODEL];
__device__ float g_diag[2*NBH*NSEQ];
__device__ float g_pksum[NBH*NFEAT];
__device__ float g_offq[NBH*NSEQ];          // diag_q + rowmax per q row
__device__ float g_den[NBH*NSEQ];
__device__ float g_im2col[TOK*256];
__device__ float g_pwT[DMODEL*256];
__device__ unsigned g_kmax;
__device__ float g_wt_qkv[NDEPTH*2304*768];
__device__ float g_wt_ao [NDEPTH*768*768];
__device__ float g_wt_ff1[NDEPTH*3072*768];
__device__ float g_wt_ff2[NDEPTH*768*3072];

// ---------------- helpers ----------------
__device__ __forceinline__ unsigned enc_f(float f){
    unsigned u = __float_as_uint(f);
    return (u & 0x80000000u) ? ~u : (u | 0x80000000u);
}
__device__ __forceinline__ float dec_f(unsigned e){
    return (e & 0x80000000u) ? __uint_as_float(e ^ 0x80000000u) : __uint_as_float(~e);
}
__device__ __forceinline__ float wsum(float v){
    #pragma unroll
    for (int o = 16; o > 0; o >>= 1) v += __shfl_xor_sync(0xffffffffu, v, o);
    return v;
}
__device__ __forceinline__ float wmax(float v){
    #pragma unroll
    for (int o = 16; o > 0; o >>= 1) v = fmaxf(v, __shfl_xor_sync(0xffffffffu, v, o));
    return v;
}
__device__ __forceinline__ float rtf32(float x){
    uint32_t o; asm("cvt.rna.tf32.f32 %0, %1;" : "=r"(o) : "f"(x));
    return __uint_as_float(o);
}
__device__ __forceinline__ uint32_t smem_u32(const void* p){
    uint32_t a;
    asm("{ .reg .u64 t; cvta.to.shared.u64 t, %1; cvt.u32.u64 %0, t; }" : "=r"(a) : "l"(p));
    return a;
}
__device__ __forceinline__ void mma_tf32(float* c, const float* a, const float* b){
    asm volatile(
        "mma.sync.aligned.m16n8k8.row.col.f32.tf32.tf32.f32 "
        "{%0,%1,%2,%3}, {%4,%5,%6,%7}, {%8,%9}, {%0,%1,%2,%3};"
        : "+f"(c[0]), "+f"(c[1]), "+f"(c[2]), "+f"(c[3])
        : "r"(__float_as_uint(a[0])), "r"(__float_as_uint(a[1])),
          "r"(__float_as_uint(a[2])), "r"(__float_as_uint(a[3])),
          "r"(__float_as_uint(b[0])), "r"(__float_as_uint(b[1])));
}
#define CPA16(saddr, gptr) \
    asm volatile("cp.async.cg.shared.global [%0], [%1], 16;" :: "r"(saddr), "l"(gptr))
__device__ __forceinline__ float phix(float v, float off){
    return rtf32((expf(v - off) + 1e-4f)*0.0625f);
}

// ---------------- tf32 mma.sync GEMM: 3-stage, 2 CTAs/SM ----------------
#define SSTRIDE 36
#define STAGEF  (2*128*SSTRIDE)
#define GEMM_SMEM (3*STAGEF*4)
__global__ void __launch_bounds__(128, 2) gemm_tc(
    const float* __restrict__ A, const float* __restrict__ WT,
    const float* __restrict__ bias, float* __restrict__ C,
    int K, int Ncols, int ep, const float* __restrict__ aux)
{
    extern __shared__ float sm[];
    int tid = threadIdx.x, lane = tid & 31, wid = tid >> 5;
    int wm = wid & 1, wn = wid >> 1;
    int n0 = blockIdx.x*128, m0 = blockIdx.y*128;
    int NC = K >> 5;
    uint32_t sb = smem_u32(sm);

    auto ldstage = [&](int s, int c){
        uint32_t abase = sb + (uint32_t)s*STAGEF*4;
        const float* Ag = A  + (size_t)m0*K + c*32;
        const float* Bg = WT + (size_t)n0*K + c*32;
        #pragma unroll
        for (int i = 0; i < 8; i++){
            int p = tid + i*128; int r = p >> 3, c4 = p & 7;
            CPA16(abase + (uint32_t)(r*SSTRIDE + c4*4)*4, Ag + (size_t)r*K + c4*4);
        }
        #pragma unroll
        for (int i = 0; i < 8; i++){
            int p = tid + i*128; int r = p >> 3, c4 = p & 7;
            CPA16(abase + (uint32_t)(128*SSTRIDE + r*SSTRIDE + c4*4)*4, Bg + (size_t)r*K + c4*4);
        }
        asm volatile("cp.async.commit_group;");
    };

    float acc[4][8][4];
    #pragma unroll
    for (int mt = 0; mt < 4; mt++)
        #pragma unroll
        for (int nt = 0; nt < 8; nt++)
            #pragma unroll
            for (int r = 0; r < 4; r++) acc[mt][nt][r] = 0.f;

    ldstage(0, 0); ldstage(1, 1); ldstage(2, 2);
    int lq = lane >> 2, lr = lane & 3;

    for (int c = 0; c < NC; c++){
        int pend = NC - 1 - c;
        if (pend >= 2)      asm volatile("cp.async.wait_group 2;" ::: "memory");
        else if (pend == 1) asm volatile("cp.async.wait_group 1;" ::: "memory");
        else                asm volatile("cp.async.wait_group 0;" ::: "memory");
        __syncthreads();

        const float* As = sm + (c % 3)*STAGEF;
        const float* Bs = As + 128*SSTRIDE;

        #pragma unroll
        for (int k8 = 0; k8 < 4; k8++){
            int kb = k8*8 + lr;
            float a[4][4], b[8][2];
            int ar = wm*64 + lq;
            #pragma unroll
            for (int mt = 0; mt < 4; mt++){
                const float* p0 = As + (size_t)(ar + mt*16)*SSTRIDE + kb;
                const float* p1 = As + (size_t)(ar + mt*16 + 8)*SSTRIDE + kb;
                a[mt][0] = p0[0]; a[mt][1] = p1[0];
                a[mt][2] = p0[4]; a[mt][3] = p1[4];
            }
            int br = wn*64 + lq;
            #pragma unroll
            for (int nt = 0; nt < 8; nt++){
                const float* p = Bs + (size_t)(br + nt*8)*SSTRIDE + kb;
                b[nt][0] = p[0]; b[nt][1] = p[4];
            }
            #pragma unroll
            for (int mt = 0; mt < 4; mt++)
                #pragma unroll
                for (int nt = 0; nt < 8; nt++)
                    mma_tf32(acc[mt][nt], a[mt], b[nt]);
        }
        __syncthreads();
        if (c + 3 < NC) ldstage(c % 3, c + 3);
    }

    int row_base = m0 + wm*64 + lq;
    int col_base = n0 + wn*64 + lr*2;
    #pragma unroll
    for (int mt = 0; mt < 4; mt++){
        #pragma unroll
        for (int h = 0; h < 2; h++){
            int row = row_base + mt*16 + h*8;
            float* crow = C + (size_t)row*Ncols;
            const float* arow = aux ? (aux + (size_t)(row & 511)*DMODEL) : (const float*)0;
            #pragma unroll
            for (int nt = 0; nt < 8; nt++){
                int col = col_base + nt*8;
                float v0 = acc[mt][nt][h*2+0] + bias[col];
                float v1 = acc[mt][nt][h*2+1] + bias[col+1];
                if (ep == 0){
                    v0 = rtf32(v0); v1 = rtf32(v1);
                } else if (ep == 1){
                    v0 = rtf32(0.5f*v0*(1.0f + erff(v0*0.70710678118654752f)));
                    v1 = rtf32(0.5f*v1*(1.0f + erff(v1*0.70710678118654752f)));
                } else if (ep == 2){
                    float2 old = *(const float2*)(crow + col);
                    v0 += old.x; v1 += old.y;
                } else if (ep == 3){
                    v0 += arow[col]; v1 += arow[col+1];
                }
                float2 o; o.x = v0; o.y = v1;
                *(float2*)(crow + col) = o;
            }
        }
    }
}

// ---------------- phi_u (q+k combined) + fused diag; writes RAW u ----------------
#define PHI_SMEM (3*2*128*36*4)
__global__ void __launch_bounds__(256, 2) phi_u_mma(
    const float* __restrict__ qkv, const float* __restrict__ proj,
    float* __restrict__ uq, float* __restrict__ uk, float* __restrict__ diag)
{
    extern __shared__ float sm[];
    __shared__ float red[8];
    int tid = threadIdx.x, lane = tid & 31, wid = tid >> 5;
    int wm = wid & 3, wn = wid >> 2;
    int m0 = blockIdx.x*128, n0 = blockIdx.y*128;
    int zz = blockIdx.z;
    int bh = zz & 63, isk = zz >> 6;
    int b = bh >> 3, h = bh & 7;
    float* U = isk ? uk : uq;
    const float* Ab = qkv + (size_t)(b*512 + n0)*2304 + isk*768 + h*96;
    const float* Bb = proj + (size_t)m0*96;
    int lq = lane >> 2, lr = lane & 3;
    uint32_t sb = smem_u32(sm);

    #pragma unroll
    for (int c = 0; c < 3; c++){
        uint32_t ab = sb + (uint32_t)c*(2*128*36*4);
        #pragma unroll
        for (int i = 0; i < 4; i++){
            int p = tid + i*256; int r = p >> 3, c4 = p & 7;
            CPA16(ab + (uint32_t)(r*36 + c4*4)*4, Ab + (size_t)r*2304 + c*32 + c4*4);
        }
        #pragma unroll
        for (int i = 0; i < 4; i++){
            int p = tid + i*256; int r = p >> 3, c4 = p & 7;
            CPA16(ab + (uint32_t)(128*36 + r*36 + c4*4)*4, Bb + (size_t)r*96 + c*32 + c4*4);
        }
        asm volatile("cp.async.commit_group;");
    }

    float acc[2][8][4];
    #pragma unroll
    for (int mt = 0; mt < 2; mt++)
        #pragma unroll
        for (int nt = 0; nt < 8; nt++)
            #pragma unroll
            for (int r = 0; r < 4; r++) acc[mt][nt][r] = 0.f;

    #pragma unroll
    for (int c = 0; c < 3; c++){
        if (c == 0)      asm volatile("cp.async.wait_group 2;" ::: "memory");
        else if (c == 1) asm volatile("cp.async.wait_group 1;" ::: "memory");
        else             asm volatile("cp.async.wait_group 0;" ::: "memory");
        __syncthreads();
        const float* As = sm + c*(2*128*36);
        const float* Bs = As + 128*36;
        #pragma unroll
        for (int k8 = 0; k8 < 4; k8++){
            int kb = k8*8 + lr;
            float a[2][4], b[8][2];
            int ar = wm*32 + lq;
            #pragma unroll
            for (int mt = 0; mt < 2; mt++){
                const float* p0 = As + (size_t)(ar + mt*16)*36 + kb;
                const float* p1 = As + (size_t)(ar + mt*16 + 8)*36 + kb;
                a[mt][0] = p0[0]; a[mt][1] = p1[0];
                a[mt][2] = p0[4]; a[mt][3] = p1[4];
            }
            int bc = wn*64 + lq;
            #pragma unroll
            for (int nt = 0; nt < 8; nt++){
                const float* p = Bs + (size_t)(bc + nt*8)*36 + kb;
                b[nt][0] = p[0]; b[nt][1] = p[4];
            }
            #pragma unroll
            for (int mt = 0; mt < 2; mt++)
                #pragma unroll
                for (int nt = 0; nt < 8; nt++)
                    mma_tf32(acc[mt][nt], a[mt], b[nt]);
        }
    }

    const float cs = 0.31947155f;   // 96^{-1/4}
    float tmax = -1e30f;
    #pragma unroll
    for (int mt = 0; mt < 2; mt++){
        int n = n0 + wm*32 + mt*16 + lq;
        int m = m0 + wn*64 + lr*2;
        float* u0 = U + ((size_t)bh*512 + n)*256;
        float* u1 = U + ((size_t)bh*512 + n + 8)*256;
        #pragma unroll
        for (int nt = 0; nt < 8; nt++){
            float v0 = acc[mt][nt][0]*cs, v1 = acc[mt][nt][1]*cs;
            float v2 = acc[mt][nt][2]*cs, v3 = acc[mt][nt][3]*cs;
            float2 p0; p0.x = v0; p0.y = v1;
            float2 p1; p1.x = v2; p1.y = v3;
            *(float2*)(u0 + m + nt*8) = p0;
            *(float2*)(u1 + m + nt*8) = p1;
            tmax = fmaxf(tmax, fmaxf(fmaxf(v0, v1), fmaxf(v2, v3)));
        }
    }

    if (blockIdx.x == 0 && tid < 128){
        float s = 0.f;
        #pragma unroll
        for (int c = 0; c < 3; c++){
            const float* As = sm + c*(2*128*36) + tid*36;
            #pragma unroll
            for (int k = 0; k < 32; k++) s += As[k]*As[k];
        }
        diag[isk*32768 + bh*512 + n0 + tid] = 0.05103103631f * s;
    }

    if (isk){
        tmax = wmax(tmax);
        if (lane == 0) red[wid] = tmax;
        __syncthreads();
        if (tid == 0){
            float m = red[0];
            #pragma unroll
            for (int i = 1; i < 8; i++) m = fmaxf(m, red[i]);
            atomicMax(&g_kmax, enc_f(m));
        }
    }
}

// ---------------- ctx: exp(pk) fused in smem + column sums -> ps ----------------
#define CTX_SV 104
#define CTX_SP 136
#define CTX_STAGEF (32*CTX_SV + 32*CTX_SP)
#define CTX_SMEM (3*CTX_STAGEF*4)
__global__ void __launch_bounds__(256, 2) ctx_mma(
    const float* __restrict__ uk, const float* __restrict__ qkv,
    const float* __restrict__ diag, float* __restrict__ ctxT,
    float* __restrict__ ps)
{
    extern __shared__ float sm[];
    __shared__ float redc[128];
    int tid = threadIdx.x, lane = tid & 31, wid = tid >> 5;
    int wm = wid & 1, wn = wid >> 1;
    int m0 = blockIdx.x*128, bh = blockIdx.y;
    int b = bh >> 3, h = bh & 7;
    const float* Vb = qkv + (size_t)(b*512)*2304 + 1536 + h*96;
    const float* Pb = uk + (size_t)(bh*512)*256 + m0;
    const float* dgk = diag + 32768 + bh*512;
    float kst = dec_f(g_kmax);
    int lq = lane >> 2, lr = lane & 3;
    uint32_t sb = smem_u32(sm);

    auto ldstage = [&](int s, int c){
        uint32_t ab = sb + (uint32_t)s*CTX_STAGEF*4;
        #pragma unroll
        for (int i = 0; i < 3; i++){
            int p = tid + i*256; int r = p/24, cc = p - r*24;
            CPA16(ab + (uint32_t)(r*CTX_SV + cc*4)*4, Vb + (size_t)(c*32 + r)*2304 + cc*4);
        }
        #pragma unroll
        for (int i = 0; i < 4; i++){
            int p = tid + i*256; int r = p >> 5, cc = p & 31;
            CPA16(ab + (uint32_t)(32*CTX_SV + r*CTX_SP + cc*4)*4,
                  Pb + (size_t)(c*32 + r)*256 + cc*4);
        }
        asm volatile("cp.async.commit_group;");
    };

    float acc[3][4][4];
    #pragma unroll
    for (int mt = 0; mt < 3; mt++)
        #pragma unroll
        for (int nt = 0; nt < 4; nt++)
            #pragma unroll
            for (int r = 0; r < 4; r++) acc[mt][nt][r] = 0.f;

    ldstage(0, 0); ldstage(1, 1); ldstage(2, 2);

    // column-sum state: thread owns col (tid&127), row-half (tid>>7)
    int cme = tid & 127, rh = tid >> 7;
    float colsum = 0.f;

    for (int c = 0; c < 16; c++){
        int pend = 15 - c;
        if (pend >= 2)      asm volatile("cp.async.wait_group 2;" ::: "memory");
        else if (pend == 1) asm volatile("cp.async.wait_group 1;" ::: "memory");
        else                asm volatile("cp.async.wait_group 0;" ::: "memory");
        __syncthreads();
        const float* Vs = sm + (c % 3)*CTX_STAGEF;
        float* Ps = (float*)(Vs + 32*CTX_SV);

        // exp-transform pk tile in smem: 32 rows x 128 cols
        {
            int r = tid >> 3, g = tid & 7;
            float off = dgk[c*32 + r] + kst;
            float* rowp = Ps + (size_t)r*CTX_SP + g*16;
            #pragma unroll
            for (int j = 0; j < 16; j++)
                rowp[j] = phix(rowp[j], off);
        }
        __syncthreads();

        #pragma unroll
        for (int k8 = 0; k8 < 4; k8++){
            int kb = k8*8 + lr;
            float a[3][4], bfr[4][2];
            int er = wm*48 + lq;
            #pragma unroll
            for (int mt = 0; mt < 3; mt++){
                a[mt][0] = Vs[(size_t)kb*CTX_SV + er + mt*16];
                a[mt][1] = Vs[(size_t)kb*CTX_SV + er + mt*16 + 8];
                a[mt][2] = Vs[(size_t)(kb+4)*CTX_SV + er + mt*16];
                a[mt][3] = Vs[(size_t)(kb+4)*CTX_SV + er + mt*16 + 8];
            }
            int mc = wn*32 + lq;
            #pragma unroll
            for (int nt = 0; nt < 4; nt++){
                bfr[nt][0] = Ps[(size_t)kb*CTX_SP + mc + nt*8];
                bfr[nt][1] = Ps[(size_t)(kb+4)*CTX_SP + mc + nt*8];
            }
            #pragma unroll
            for (int mt = 0; mt < 3; mt++)
                #pragma unroll
                for (int nt = 0; nt < 4; nt++)
                    mma_tf32(acc[mt][nt], a[mt], bfr[nt]);
        }

        // column partial sums from transformed tile
        {
            const float* p = Ps + (size_t)(rh*16)*CTX_SP + cme;
            float s = 0.f;
            #pragma unroll
            for (int j = 0; j < 16; j++) s += p[(size_t)j*CTX_SP];
            colsum += s;
        }
        __syncthreads();
        if (c + 3 < 16) ldstage(c % 3, c + 3);
    }

    // deterministic two-half combine -> ps
    if (rh == 0) redc[cme] = colsum;
    __syncthreads();
    if (rh == 1) ps[bh*256 + m0 + cme] = redc[cme] + colsum;

    #pragma unroll
    for (int mt = 0; mt < 3; mt++){
        int e = wm*48 + mt*16 + lq;
        int m = m0 + wn*32 + lr*2;
        float* c0 = ctxT + ((size_t)bh*96 + e)*256;
        float* c1 = ctxT + ((size_t)bh*96 + e + 8)*256;
        #pragma unroll
        for (int nt = 0; nt < 4; nt++){
            float2 p0; p0.x = rtf32(acc[mt][nt][0]); p0.y = rtf32(acc[mt][nt][1]);
            float2 p1; p1.x = rtf32(acc[mt][nt][2]); p1.y = rtf32(acc[mt][nt][3]);
            *(float2*)(c0 + m + nt*8) = p0;
            *(float2*)(c1 + m + nt*8) = p1;
        }
    }
}

// ---------------- den + off from raw uq (no write-back) ----------------
__global__ void den_only(const float* __restrict__ U, const float* __restrict__ diagq,
                         const float* __restrict__ ps, float* __restrict__ den,
                         float* __restrict__ offq)
{
    int gw = blockIdx.x*8 + (threadIdx.x >> 5);
    int lane = threadIdx.x & 31;
    int bh = gw >> 9;
    const float* u = U + (size_t)gw*256;
    const float* s = ps + bh*256;
    float v[8]; float m = -1e30f;
    #pragma unroll
    for (int i = 0; i < 8; i++){ v[i] = u[lane + 32*i]; m = fmaxf(m, v[i]); }
    m = wmax(m);
    float off = diagq[gw] + m;
    float a = 0.f;
    #pragma unroll
    for (int i = 0; i < 8; i++)
        a += phix(v[i], off) * s[lane + 32*i];
    a = wsum(a);
    if (lane == 0){ den[gw] = a; offq[gw] = off; }
}

// ---------------- attn: exp(pq) fused in smem ----------------
#define ATT_STAGEF (128*36 + 96*36)
#define ATT_SMEM (3*ATT_STAGEF*4)
__global__ void __launch_bounds__(256, 2) attn_out_mma(
    const float* __restrict__ uq, const float* __restrict__ ctxT,
    const float* __restrict__ den, const float* __restrict__ offq,
    float* __restrict__ attn)
{
    extern __shared__ float sm[];
    int tid = threadIdx.x, lane = tid & 31, wid = tid >> 5;
    int wm = wid & 3, wn = wid >> 2;
    int n0 = blockIdx.x*128, bh = blockIdx.y;
    int b = bh >> 3, h = bh & 7;
    const float* Ab = uq + ((size_t)bh*512 + n0)*256;
    const float* Bb = ctxT + (size_t)bh*96*256;
    const float* offb = offq + bh*512 + n0;
    int lq = lane >> 2, lr = lane & 3;
    uint32_t sb = smem_u32(sm);

    auto ldstage = [&](int s, int c){
        uint32_t ab = sb + (uint32_t)s*ATT_STAGEF*4;
        #pragma unroll
        for (int i = 0; i < 4; i++){
            int p = tid + i*256; int r = p >> 3, c4 = p & 7;
            CPA16(ab + (uint32_t)(r*36 + c4*4)*4, Ab + (size_t)r*256 + c*32 + c4*4);
        }
        #pragma unroll
        for (int i = 0; i < 3; i++){
            int p = tid + i*256; int r = p >> 3, c4 = p & 7;
            CPA16(ab + (uint32_t)(128*36 + r*36 + c4*4)*4, Bb + (size_t)r*256 + c*32 + c4*4);
        }
        asm volatile("cp.async.commit_group;");
    };

    float acc[2][6][4];
    #pragma unroll
    for (int mt = 0; mt < 2; mt++)
        #pragma unroll
        for (int nt = 0; nt < 6; nt++)
            #pragma unroll
            for (int r = 0; r < 4; r++) acc[mt][nt][r] = 0.f;

    ldstage(0, 0); ldstage(1, 1); ldstage(2, 2);

    for (int c = 0; c < 8; c++){
        int pend = 7 - c;
        if (pend >= 2)      asm volatile("cp.async.wait_group 2;" ::: "memory");
        else if (pend == 1) asm volatile("cp.async.wait_group 1;" ::: "memory");
        else                asm volatile("cp.async.wait_group 0;" ::: "memory");
        __syncthreads();
        float* As = sm + (c % 3)*ATT_STAGEF;
        const float* Bs = As + 128*36;

        // exp-transform pq tile in smem: 128 rows x 32 cols
        {
            int r = tid >> 1, hh = tid & 1;
            float off = offb[r];
            float* rowp = As + (size_t)r*36 + hh*16;
            #pragma unroll
            for (int j = 0; j < 16; j++)
                rowp[j] = phix(rowp[j], off);
        }
        __syncthreads();

        #pragma unroll
        for (int k8 = 0; k8 < 4; k8++){
            int kb = k8*8 + lr;
            float a[2][4], bfr[6][2];
            int ar = wm*32 + lq;
            #pragma unroll
            for (int mt = 0; mt < 2; mt++){
                const float* p0 = As + (size_t)(ar + mt*16)*36 + kb;
                const float* p1 = As + (size_t)(ar + mt*16 + 8)*36 + kb;
                a[mt][0] = p0[0]; a[mt][1] = p1[0];
                a[mt][2] = p0[4]; a[mt][3] = p1[4];
            }
            int ec = wn*48 + lq;
            #pragma unroll
            for (int nt = 0; nt < 6; nt++){
                const float* p = Bs + (size_t)(ec + nt*8)*36 + kb;
                bfr[nt][0] = p[0]; bfr[nt][1] = p[4];
            }
            #pragma unroll
            for (int mt = 0; mt < 2; mt++)
                #pragma unroll
                for (int nt = 0; nt < 6; nt++)
                    mma_tf32(acc[mt][nt], a[mt], bfr[nt]);
        }
        __syncthreads();
        if (c + 3 < 8) ldstage(c % 3, c + 3);
    }

    #pragma unroll
    for (int mt = 0; mt < 2; mt++){
        int n = n0 + wm*32 + mt*16 + lq;
        float d0 = 1.f/den[bh*512 + n];
        float d1 = 1.f/den[bh*512 + n + 8];
        float* o0 = attn + (size_t)(b*512 + n)*768 + h*96;
        float* o1 = attn + (size_t)(b*512 + n + 8)*768 + h*96;
        int e = wn*48 + lr*2;
        #pragma unroll
        for (int nt = 0; nt < 6; nt++){
            float2 p0; p0.x = rtf32(acc[mt][nt][0]*d0); p0.y = rtf32(acc[mt][nt][1]*d0);
            float2 p1; p1.x = rtf32(acc[mt][nt][2]*d1); p1.y = rtf32(acc[mt][nt][3]*d1);
            *(float2*)(o0 + e + nt*8) = p0;
            *(float2*)(o1 + e + nt*8) = p1;
        }
    }
}

// ---------------- prep kernels ----------------
__global__ void transpose_w(const float* __restrict__ src, float* __restrict__ dst,
                            int K, int N)
{
    __shared__ float t[32][33];
    int n0 = blockIdx.x*32, k0 = blockIdx.y*32;
    size_t off = (size_t)blockIdx.z * (size_t)K * N;
    src += off; dst += off;
    int tx = threadIdx.x & 31, ty = threadIdx.x >> 5;
    #pragma unroll
    for (int i = 0; i < 32; i += 8)
        t[ty+i][tx] = src[(size_t)(k0+ty+i)*N + n0+tx];
    __syncthreads();
    #pragma unroll
    for (int i = 0; i < 32; i += 8)
        dst[(size_t)(n0+ty+i)*K + k0+tx] = rtf32(t[tx][ty+i]);
}

__global__ void copy_round(const float* __restrict__ src, float* __restrict__ dst){
    int i = blockIdx.x*256 + threadIdx.x;
    dst[i] = rtf32(src[i]);
}

__global__ void im2col_kernel(const float* __restrict__ mel, float* __restrict__ dst){
    int idx = blockIdx.x*256 + threadIdx.x;
    int pg = idx >> 8, k = idx & 255;
    int b = pg >> 9, p = pg & 511;
    int oh = p >> 3, ow = p & 7;
    int i = k >> 4, j = k & 15;
    dst[idx] = rtf32(mel[(size_t)b*131072 + (size_t)(oh*16 + i)*128 + ow*16 + j]);
}

// ---------------- layernorm (also resets g_kmax) ----------------
__global__ void ln_kernel(const float* __restrict__ X, const float* __restrict__ sc,
                          const float* __restrict__ bb, float* __restrict__ Y)
{
    __shared__ float s1[8], s2[8];
    int row = blockIdx.x, tid = threadIdx.x;
    if (row == 0 && tid == 0) g_kmax = 0u;
    int lane = tid & 31, wid = tid >> 5;
    const float* xr = X + (size_t)row*DMODEL;
    float v[3]; float sum = 0.f, sq = 0.f;
    #pragma unroll
    for (int i = 0; i < 3; i++){
        v[i] = xr[tid + 256*i];
        sum += v[i]; sq += v[i]*v[i];
    }
    sum = wsum(sum); sq = wsum(sq);
    if (lane == 0){ s1[wid] = sum; s2[wid] = sq; }
    __syncthreads();
    if (tid == 0){
        float a = 0.f, b2 = 0.f;
        #pragma unroll
        for (int i = 0; i < 8; i++){ a += s1[i]; b2 += s2[i]; }
        s1[0] = a; s2[0] = b2;
    }
    __syncthreads();
    float mean = s1[0]*(1.f/768.f);
    float var  = s2[0]*(1.f/768.f) - mean*mean;
    float rstd = rsqrtf(var + 1e-5f);
    float* yr = Y + (size_t)row*DMODEL;
    #pragma unroll
    for (int i = 0; i < 3; i++){
        int d = tid + 256*i;
        yr[d] = rtf32((v[i] - mean)*rstd*sc[d] + bb[d]);
    }
}

// ---------------- mask head ----------------
__global__ void mask_kernel(const float* __restrict__ X, const float* __restrict__ mw,
                            const float* __restrict__ mb, float* __restrict__ out)
{
    int row = blockIdx.x;
    int tid = threadIdx.x;
    int w = tid >> 5, lane = tid & 31;
    const float* xr = X + (size_t)row*768;
    float s = 0.f;
    for (int d = lane; d < 768; d += 32) s += xr[d]*mw[d*4 + w];
    s = wsum(s);
    if (lane == 0){
        float logit = s + mb[w];
        int b = row >> 9, n = row & 511;
        out[((size_t)b*4 + w)*512 + n] = 1.f/(1.f + expf(-logit));
    }
}

// ---------------- driver ----------------
extern "C" void kernel_launch(void* const* d_in, const int* in_sizes, int n_in,
                              void* d_out, int out_size)
{
    (void)in_sizes; (void)n_in; (void)out_size;
    const float* mel     = (const float*)d_in[0];
    const float* patch_w = (const float*)d_in[1];
    const float* patch_b = (const float*)d_in[2];
    const float* pos     = (const float*)d_in[3];
    const float* proj    = (const float*)d_in[4];
    const float* ln1_s   = (const float*)d_in[5];
    const float* ln1_b   = (const float*)d_in[6];
    const float* qkv_w   = (const float*)d_in[7];
    const float* qkv_b   = (const float*)d_in[8];
    const float* ao_w    = (const float*)d_in[9];
    const float* ao_b    = (const float*)d_in[10];
    const float* ln2_s   = (const float*)d_in[11];
    const float* ln2_b   = (const float*)d_in[12];
    const float* ff1_w   = (const float*)d_in[13];
    const float* ff1_b   = (const float*)d_in[14];
    const float* ff2_w   = (const float*)d_in[15];
    const float* ff2_b   = (const float*)d_in[16];
    const float* mask_w  = (const float*)d_in[17];
    const float* mask_b  = (const float*)d_in[18];
    float* out = (float*)d_out;

    float *x, *lnb, *qkv, *ffb, *uq, *uk, *ctxb, *attn, *diag, *ps, *offq, *den, *im2, *pwT;
    float *wtq, *wtao, *wtf1, *wtf2;
    cudaGetSymbolAddress((void**)&x,    g_x);
    cudaGetSymbolAddress((void**)&lnb,  g_lnbuf);
    cudaGetSymbolAddress((void**)&qkv,  g_qkv);
    cudaGetSymbolAddress((void**)&ffb,  g_ffbuf);
    cudaGetSymbolAddress((void**)&uq,   g_uq);
    cudaGetSymbolAddress((void**)&uk,   g_uk);
    cudaGetSymbolAddress((void**)&ctxb, g_ctxb);
    cudaGetSymbolAddress((void**)&attn, g_attn);
    cudaGetSymbolAddress((void**)&diag, g_diag);
    cudaGetSymbolAddress((void**)&ps,   g_pksum);
    cudaGetSymbolAddress((void**)&offq, g_offq);
    cudaGetSymbolAddress((void**)&den,  g_den);
    cudaGetSymbolAddress((void**)&im2,  g_im2col);
    cudaGetSymbolAddress((void**)&pwT,  g_pwT);
    cudaGetSymbolAddress((void**)&wtq,  g_wt_qkv);
    cudaGetSymbolAddress((void**)&wtao, g_wt_ao);
    cudaGetSymbolAddress((void**)&wtf1, g_wt_ff1);
    cudaGetSymbolAddress((void**)&wtf2, g_wt_ff2);

    cudaFuncSetAttribute(gemm_tc, cudaFuncAttributeMaxDynamicSharedMemorySize, GEMM_SMEM);
    cudaFuncSetAttribute(phi_u_mma, cudaFuncAttributeMaxDynamicSharedMemorySize, PHI_SMEM);
    cudaFuncSetAttribute(ctx_mma, cudaFuncAttributeMaxDynamicSharedMemorySize, CTX_SMEM);
    cudaFuncSetAttribute(attn_out_mma, cudaFuncAttributeMaxDynamicSharedMemorySize, ATT_SMEM);

    // weight prep
    copy_round<<<768, 256>>>(patch_w, pwT);
    transpose_w<<<dim3(72, 24, 6), 256>>>(qkv_w, wtq, 768, 2304);
    transpose_w<<<dim3(24, 24, 6), 256>>>(ao_w,  wtao, 768, 768);
    transpose_w<<<dim3(96, 24, 6), 256>>>(ff1_w, wtf1, 768, 3072);
    transpose_w<<<dim3(24, 96, 6), 256>>>(ff2_w, wtf2, 3072, 768);

    // patch embed
    im2col_kernel<<<4096, 256>>>(mel, im2);
    gemm_tc<<<dim3(6, 32), 128, GEMM_SMEM>>>(im2, pwT, patch_b, x, 256, 768, 3, pos);

    for (int l = 0; l < NDEPTH; l++){
        ln_kernel<<<4096, 256>>>(x, ln1_s + l*768, ln1_b + l*768, lnb);
        gemm_tc<<<dim3(18, 32), 128, GEMM_SMEM>>>(
            lnb, wtq + (size_t)l*2304*768, qkv_b + l*2304, qkv, 768, 2304, 0, 0);
        phi_u_mma<<<dim3(2, 4, 128), 256, PHI_SMEM>>>(qkv, proj, uq, uk, diag);
        ctx_mma<<<dim3(2, 64), 256, CTX_SMEM>>>(uk, qkv, diag, ctxb, ps);
        den_only<<<4096, 256>>>(uq, diag, ps, den, offq);
        attn_out_mma<<<dim3(4, 64), 256, ATT_SMEM>>>(uq, ctxb, den, offq, attn);
        gemm_tc<<<dim3(6, 32), 128, GEMM_SMEM>>>(
            attn, wtao + (size_t)l*768*768, ao_b + l*768, x, 768, 768, 2, 0);
        ln_kernel<<<4096, 256>>>(x, ln2_s + l*768, ln2_b + l*768, lnb);
        gemm_tc<<<dim3(24, 32), 128, GEMM_SMEM>>>(
            lnb, wtf1 + (size_t)l*768*3072, ff1_b + l*3072, ffb, 768, 3072, 1, 0);
        gemm_tc<<<dim3(6, 32), 128, GEMM_SMEM>>>(
            ffb, wtf2 + (size_t)l*3072*768, ff2_b + l*768, x, 3072, 768, 2, 0);
    }

    mask_kernel<<<4096, 128>>>(x, mask_w, mask_b, out);
}

// round 9
// speedup vs baseline: 1.5676x; 1.5676x over previous
#include <cuda_runtime.h>
#include <cuda_fp16.h>
#include <math.h>
#include <stdint.h>

#define TOK    4096
#define DMODEL 768
#define NSEQ   512
#define NHEAD  8
#define DHEAD  96
#define NFEAT  256
#define NBH    64
#define NFF    3072
#define NDEPTH 6

// ---------------- scratch ----------------
__device__ float  g_x[TOK*DMODEL];
__device__ __half g_lnbuf[TOK*DMODEL];
__device__ __half g_qkv[TOK*3*DMODEL];
__device__ __half g_ffbuf[TOK*NFF];
__device__ float  g_uq[NBH*NSEQ*NFEAT];
__device__ float  g_uk[NBH*NSEQ*NFEAT];
__device__ __half g_ctxb[NBH*DHEAD*NFEAT];   // ctxT [bh][96e][256m] fp16
__device__ __half g_attn[TOK*DMODEL];
__device__ float  g_diag[2*NBH*NSEQ];
__device__ float  g_pksum[NBH*NFEAT];
__device__ float  g_offq[NBH*NSEQ];
__device__ float  g_den[NBH*NSEQ];
__device__ __half g_im2col[TOK*256];
__device__ __half g_pwT[DMODEL*256];
__device__ __half g_projh[NFEAT*DHEAD];      // fp16(proj * 96^-1/4)
__device__ unsigned g_kmax;
__device__ __half g_wt_qkv[NDEPTH*2304*768];
__device__ __half g_wt_ao [NDEPTH*768*768];
__device__ __half g_wt_ff1[NDEPTH*3072*768];
__device__ __half g_wt_ff2[NDEPTH*768*3072];

// ---------------- helpers ----------------
__device__ __forceinline__ unsigned enc_f(float f){
    unsigned u = __float_as_uint(f);
    return (u & 0x80000000u) ? ~u : (u | 0x80000000u);
}
__device__ __forceinline__ float dec_f(unsigned e){
    return (e & 0x80000000u) ? __uint_as_float(e ^ 0x80000000u) : __uint_as_float(~e);
}
__device__ __forceinline__ float wsum(float v){
    #pragma unroll
    for (int o = 16; o > 0; o >>= 1) v += __shfl_xor_sync(0xffffffffu, v, o);
    return v;
}
__device__ __forceinline__ float wmax(float v){
    #pragma unroll
    for (int o = 16; o > 0; o >>= 1) v = fmaxf(v, __shfl_xor_sync(0xffffffffu, v, o));
    return v;
}
__device__ __forceinline__ uint32_t smem_u32(const void* p){
    uint32_t a;
    asm("{ .reg .u64 t; cvta.to.shared.u64 t, %1; cvt.u32.u64 %0, t; }" : "=r"(a) : "l"(p));
    return a;
}
__device__ __forceinline__ void mma_f16(float* c, const uint32_t* a, const uint32_t* b){
    asm volatile(
        "mma.sync.aligned.m16n8k16.row.col.f32.f16.f16.f32 "
        "{%0,%1,%2,%3}, {%4,%5,%6,%7}, {%8,%9}, {%0,%1,%2,%3};"
        : "+f"(c[0]), "+f"(c[1]), "+f"(c[2]), "+f"(c[3])
        : "r"(a[0]), "r"(a[1]), "r"(a[2]), "r"(a[3]), "r"(b[0]), "r"(b[1]));
}
#define CPA16(saddr, gptr) \
    asm volatile("cp.async.cg.shared.global [%0], [%1], 16;" :: "r"(saddr), "l"(gptr))
__device__ __forceinline__ __half phih(float v, float off){
    return __float2half_rn((expf(v - off) + 1e-4f)*0.0625f);
}
#define LDH2(x) (*(const uint32_t*)(x))

// ---------------- fp16 mma GEMM: C[4096,N] = A @ WT^T, BK=64, 3-stage, 2 CTA/SM ----
#define SH 72                       // half stride per row
#define STAGEH (2*128*SH)           // halfs per stage
#define GEMM_SMEM (3*STAGEH*2)      // bytes = 110592
__global__ void __launch_bounds__(128, 2) gemm_tc(
    const __half* __restrict__ A, const __half* __restrict__ WT,
    const float* __restrict__ bias, float* __restrict__ C,
    int K, int Ncols, int ep, const float* __restrict__ aux)
{
    extern __shared__ __half smh[];
    int tid = threadIdx.x, lane = tid & 31, wid = tid >> 5;
    int wm = wid & 1, wn = wid >> 1;
    int n0 = blockIdx.x*128, m0 = blockIdx.y*128;
    int NC = K >> 6;
    uint32_t sb = smem_u32(smh);

    auto ldstage = [&](int s, int c){
        uint32_t abase = sb + (uint32_t)s*STAGEH*2;
        const __half* Ag = A  + (size_t)m0*K + c*64;
        const __half* Bg = WT + (size_t)n0*K + c*64;
        #pragma unroll
        for (int i = 0; i < 8; i++){
            int p = tid + i*128; int r = p >> 3, c8 = p & 7;
            CPA16(abase + (uint32_t)(r*SH + c8*8)*2, Ag + (size_t)r*K + c8*8);
        }
        #pragma unroll
        for (int i = 0; i < 8; i++){
            int p = tid + i*128; int r = p >> 3, c8 = p & 7;
            CPA16(abase + (uint32_t)(128*SH + r*SH + c8*8)*2, Bg + (size_t)r*K + c8*8);
        }
        asm volatile("cp.async.commit_group;");
    };

    float acc[4][8][4];
    #pragma unroll
    for (int mt = 0; mt < 4; mt++)
        #pragma unroll
        for (int nt = 0; nt < 8; nt++)
            #pragma unroll
            for (int r = 0; r < 4; r++) acc[mt][nt][r] = 0.f;

    ldstage(0, 0); ldstage(1, 1); ldstage(2, 2);
    int lq = lane >> 2, lr = lane & 3;

    for (int c = 0; c < NC; c++){
        int pend = NC - 1 - c;
        if (pend >= 2)      asm volatile("cp.async.wait_group 2;" ::: "memory");
        else if (pend == 1) asm volatile("cp.async.wait_group 1;" ::: "memory");
        else                asm volatile("cp.async.wait_group 0;" ::: "memory");
        __syncthreads();

        const __half* As = smh + (c % 3)*STAGEH;
        const __half* Bs = As + 128*SH;

        #pragma unroll
        for (int ks = 0; ks < 4; ks++){
            int kb = ks*16 + 2*lr;
            uint32_t a[4][4], b[8][2];
            int ar = wm*64 + lq;
            #pragma unroll
            for (int mt = 0; mt < 4; mt++){
                const __half* p0 = As + (size_t)(ar + mt*16)*SH + kb;
                const __half* p1 = As + (size_t)(ar + mt*16 + 8)*SH + kb;
                a[mt][0] = LDH2(p0); a[mt][1] = LDH2(p1);
                a[mt][2] = LDH2(p0 + 8); a[mt][3] = LDH2(p1 + 8);
            }
            int br = wn*64 + lq;
            #pragma unroll
            for (int nt = 0; nt < 8; nt++){
                const __half* p = Bs + (size_t)(br + nt*8)*SH + kb;
                b[nt][0] = LDH2(p); b[nt][1] = LDH2(p + 8);
            }
            #pragma unroll
            for (int mt = 0; mt < 4; mt++)
                #pragma unroll
                for (int nt = 0; nt < 8; nt++)
                    mma_f16(acc[mt][nt], a[mt], b[nt]);
        }
        __syncthreads();
        if (c + 3 < NC) ldstage(c % 3, c + 3);
    }

    int row_base = m0 + wm*64 + lq;
    int col_base = n0 + wn*64 + lr*2;
    __half* C16 = (__half*)C;
    #pragma unroll
    for (int mt = 0; mt < 4; mt++){
        #pragma unroll
        for (int h = 0; h < 2; h++){
            int row = row_base + mt*16 + h*8;
            const float* arow = aux ? (aux + (size_t)(row & 511)*DMODEL) : (const float*)0;
            #pragma unroll
            for (int nt = 0; nt < 8; nt++){
                int col = col_base + nt*8;
                float v0 = acc[mt][nt][h*2+0] + bias[col];
                float v1 = acc[mt][nt][h*2+1] + bias[col+1];
                if (ep == 0){
                    *(__half2*)(C16 + (size_t)row*Ncols + col) = __floats2half2_rn(v0, v1);
                } else if (ep == 1){
                    v0 = 0.5f*v0*(1.0f + erff(v0*0.70710678118654752f));
                    v1 = 0.5f*v1*(1.0f + erff(v1*0.70710678118654752f));
                    *(__half2*)(C16 + (size_t)row*Ncols + col) = __floats2half2_rn(v0, v1);
                } else {
                    float* crow = C + (size_t)row*Ncols;
                    if (ep == 2){
                        float2 old = *(const float2*)(crow + col);
                        v0 += old.x; v1 += old.y;
                    } else {
                        v0 += arow[col]; v1 += arow[col+1];
                    }
                    float2 o; o.x = v0; o.y = v1;
                    *(float2*)(crow + col) = o;
                }
            }
        }
    }
}

// ---------------- phi_u (q+k) fp16 mma, K=96, single-shot smem, fused diag ----------
#define PSH 104
#define PHI_SMEM (2*128*PSH*2)
__global__ void __launch_bounds__(256, 2) phi_u_mma(
    const __half* __restrict__ qkv16, const __half* __restrict__ projh,
    float* __restrict__ uq, float* __restrict__ uk, float* __restrict__ diag)
{
    extern __shared__ __half smh[];
    __shared__ float red[8];
    int tid = threadIdx.x, lane = tid & 31, wid = tid >> 5;
    int wm = wid & 3, wn = wid >> 2;
    int m0 = blockIdx.x*128, n0 = blockIdx.y*128;
    int zz = blockIdx.z;
    int bh = zz & 63, isk = zz >> 6;
    int b = bh >> 3, h = bh & 7;
    float* U = isk ? uk : uq;
    const __half* Ab = qkv16 + (size_t)(b*512 + n0)*2304 + isk*768 + h*96;
    const __half* Bb = projh + (size_t)m0*96;
    int lq = lane >> 2, lr = lane & 3;
    uint32_t sb = smem_u32(smh);

    // 128 rows x 96 halfs = 1536 16B chunks per operand
    #pragma unroll
    for (int i = 0; i < 6; i++){
        int p = tid + i*256; int r = p/12, cc = p - r*12;
        CPA16(sb + (uint32_t)(r*PSH + cc*8)*2, Ab + (size_t)r*2304 + cc*8);
    }
    #pragma unroll
    for (int i = 0; i < 6; i++){
        int p = tid + i*256; int r = p/12, cc = p - r*12;
        CPA16(sb + (uint32_t)(128*PSH + r*PSH + cc*8)*2, Bb + (size_t)r*96 + cc*8);
    }
    asm volatile("cp.async.commit_group;");
    asm volatile("cp.async.wait_group 0;" ::: "memory");
    __syncthreads();

    const __half* As = smh;
    const __half* Bs = smh + 128*PSH;

    float acc[2][8][4];
    #pragma unroll
    for (int mt = 0; mt < 2; mt++)
        #pragma unroll
        for (int nt = 0; nt < 8; nt++)
            #pragma unroll
            for (int r = 0; r < 4; r++) acc[mt][nt][r] = 0.f;

    #pragma unroll
    for (int ks = 0; ks < 6; ks++){
        int kb = ks*16 + 2*lr;
        uint32_t a[2][4], b[8][2];
        int ar = wm*32 + lq;
        #pragma unroll
        for (int mt = 0; mt < 2; mt++){
            const __half* p0 = As + (size_t)(ar + mt*16)*PSH + kb;
            const __half* p1 = As + (size_t)(ar + mt*16 + 8)*PSH + kb;
            a[mt][0] = LDH2(p0); a[mt][1] = LDH2(p1);
            a[mt][2] = LDH2(p0 + 8); a[mt][3] = LDH2(p1 + 8);
        }
        int bc = wn*64 + lq;
        #pragma unroll
        for (int nt = 0; nt < 8; nt++){
            const __half* p = Bs + (size_t)(bc + nt*8)*PSH + kb;
            b[nt][0] = LDH2(p); b[nt][1] = LDH2(p + 8);
        }
        #pragma unroll
        for (int mt = 0; mt < 2; mt++)
            #pragma unroll
            for (int nt = 0; nt < 8; nt++)
                mma_f16(acc[mt][nt], a[mt], b[nt]);
    }

    float tmax = -1e30f;
    #pragma unroll
    for (int mt = 0; mt < 2; mt++){
        int n = n0 + wm*32 + mt*16 + lq;
        int m = m0 + wn*64 + lr*2;
        float* u0 = U + ((size_t)bh*512 + n)*256;
        float* u1 = U + ((size_t)bh*512 + n + 8)*256;
        #pragma unroll
        for (int nt = 0; nt < 8; nt++){
            float v0 = acc[mt][nt][0], v1 = acc[mt][nt][1];
            float v2 = acc[mt][nt][2], v3 = acc[mt][nt][3];
            float2 p0; p0.x = v0; p0.y = v1;
            float2 p1; p1.x = v2; p1.y = v3;
            *(float2*)(u0 + m + nt*8) = p0;
            *(float2*)(u1 + m + nt*8) = p1;
            tmax = fmaxf(tmax, fmaxf(fmaxf(v0, v1), fmaxf(v2, v3)));
        }
    }

    if (blockIdx.x == 0 && tid < 128){
        float s = 0.f;
        const __half* xr = As + (size_t)tid*PSH;
        #pragma unroll
        for (int k = 0; k < 48; k++){
            __half2 hv = *(const __half2*)(xr + 2*k);
            float f0 = __low2float(hv), f1 = __high2float(hv);
            s += f0*f0 + f1*f1;
        }
        diag[isk*32768 + bh*512 + n0 + tid] = 0.05103103631f * s;
    }

    if (isk){
        tmax = wmax(tmax);
        if (lane == 0) red[wid] = tmax;
        __syncthreads();
        if (tid == 0){
            float m = red[0];
            #pragma unroll
            for (int i = 1; i < 8; i++) m = fmaxf(m, red[i]);
            atomicMax(&g_kmax, enc_f(m));
        }
    }
}

// ---------------- ctxT[e][m] = sum_n V[n][e]*pk[n][m], fp16, transform-on-fill ------
__global__ void __launch_bounds__(256, 2) ctx_mma(
    const float* __restrict__ uk, const __half* __restrict__ qkv16,
    const float* __restrict__ diag, __half* __restrict__ ctxT,
    float* __restrict__ ps)
{
    __shared__ __half VsT[96*40];     // [e][n]
    __shared__ __half PsT[64*40];     // [m][n]
    __shared__ float redc[256];
    int tid = threadIdx.x, lane = tid & 31, wid = tid >> 5;
    int wm = wid & 1, wn = wid >> 1;  // e split 2 (48), m split 4 (16)
    int m0 = blockIdx.x*64, bh = blockIdx.y;
    int b = bh >> 3, h = bh & 7;
    const __half* Vb = qkv16 + (size_t)(b*512)*2304 + 1536 + h*96;
    const float* Pb = uk + (size_t)(bh*512)*256 + m0;
    const float* dgk = diag + 32768 + bh*512;
    float kst = dec_f(g_kmax);
    int lq = lane >> 2, lr = lane & 3;

    int fn = tid >> 3;            // n within chunk (0..31)
    int fe = (tid & 7)*12;        // e start
    int fm = (tid & 7)*8;         // m start

    uint32_t vreg[6]; float preg[8]; float off = 0.f;
    auto loadRegs = [&](int c){
        const uint32_t* vp = (const uint32_t*)(Vb + (size_t)(c*32 + fn)*2304 + fe);
        #pragma unroll
        for (int j = 0; j < 6; j++) vreg[j] = vp[j];
        const float* pr = Pb + (size_t)(c*32 + fn)*256 + fm;
        float4 q0 = *(const float4*)pr, q1 = *(const float4*)(pr + 4);
        preg[0]=q0.x; preg[1]=q0.y; preg[2]=q0.z; preg[3]=q0.w;
        preg[4]=q1.x; preg[5]=q1.y; preg[6]=q1.z; preg[7]=q1.w;
        off = dgk[c*32 + fn] + kst;
    };
    auto storeSmem = [&](){
        #pragma unroll
        for (int j = 0; j < 6; j++){
            __half2 hv = *reinterpret_cast<__half2*>(&vreg[j]);
            VsT[(fe + 2*j)*40 + fn]     = __low2half(hv);
            VsT[(fe + 2*j + 1)*40 + fn] = __high2half(hv);
        }
        #pragma unroll
        for (int j = 0; j < 8; j++)
            PsT[(fm + j)*40 + fn] = phih(preg[j], off);
    };

    float acc[3][2][4];
    #pragma unroll
    for (int mt = 0; mt < 3; mt++)
        #pragma unroll
        for (int nt = 0; nt < 2; nt++)
            #pragma unroll
            for (int r = 0; r < 4; r++) acc[mt][nt][r] = 0.f;

    loadRegs(0);
    storeSmem();
    __syncthreads();

    int csm = tid & 63, csp = tid >> 6;
    float colsum = 0.f;

    for (int c = 0; c < 16; c++){
        if (c < 15) loadRegs(c + 1);

        #pragma unroll
        for (int ks = 0; ks < 2; ks++){
            int kb = ks*16 + 2*lr;
            uint32_t a[3][4], bfr[2][2];
            int er = wm*48 + lq;
            #pragma unroll
            for (int mt = 0; mt < 3; mt++){
                const __half* p0 = VsT + (size_t)(er + mt*16)*40 + kb;
                const __half* p1 = VsT + (size_t)(er + mt*16 + 8)*40 + kb;
                a[mt][0] = LDH2(p0); a[mt][1] = LDH2(p1);
                a[mt][2] = LDH2(p0 + 8); a[mt][3] = LDH2(p1 + 8);
            }
            int bm = wn*16 + lq;
            #pragma unroll
            for (int nt = 0; nt < 2; nt++){
                const __half* p = PsT + (size_t)(bm + nt*8)*40 + kb;
                bfr[nt][0] = LDH2(p); bfr[nt][1] = LDH2(p + 8);
            }
            #pragma unroll
            for (int mt = 0; mt < 3; mt++)
                #pragma unroll
                for (int nt = 0; nt < 2; nt++)
                    mma_f16(acc[mt][nt], a[mt], bfr[nt]);
        }
        {
            const __half* p = PsT + (size_t)csm*40 + csp*8;
            float s = 0.f;
            #pragma unroll
            for (int j = 0; j < 8; j++) s += __half2float(p[j]);
            colsum += s;
        }
        __syncthreads();
        if (c < 15){
            storeSmem();
            __syncthreads();
        }
    }

    redc[tid] = colsum;
    __syncthreads();
    if (tid < 64)
        ps[bh*256 + m0 + tid] = redc[tid] + redc[tid+64] + redc[tid+128] + redc[tid+192];

    #pragma unroll
    for (int mt = 0; mt < 3; mt++){
        int e = wm*48 + mt*16 + lq;
        int m = m0 + wn*16 + lr*2;
        __half* c0 = ctxT + ((size_t)bh*96 + e)*256;
        __half* c1 = ctxT + ((size_t)bh*96 + e + 8)*256;
        #pragma unroll
        for (int nt = 0; nt < 2; nt++){
            *(__half2*)(c0 + m + nt*8) = __floats2half2_rn(acc[mt][nt][0], acc[mt][nt][1]);
            *(__half2*)(c1 + m + nt*8) = __floats2half2_rn(acc[mt][nt][2], acc[mt][nt][3]);
        }
    }
}

// ---------------- den + off from raw uq ----------------
__global__ void den_only(const float* __restrict__ U, const float* __restrict__ diagq,
                         const float* __restrict__ ps, float* __restrict__ den,
                         float* __restrict__ offq)
{
    int gw = blockIdx.x*8 + (threadIdx.x >> 5);
    int lane = threadIdx.x & 31;
    int bh = gw >> 9;
    const float* u = U + (size_t)gw*256;
    const float* s = ps + bh*256;
    float v[8]; float m = -1e30f;
    #pragma unroll
    for (int i = 0; i < 8; i++){ v[i] = u[lane + 32*i]; m = fmaxf(m, v[i]); }
    m = wmax(m);
    float off = diagq[gw] + m;
    float a = 0.f;
    #pragma unroll
    for (int i = 0; i < 8; i++)
        a += __half2float(phih(v[i], off)) * s[lane + 32*i];
    a = wsum(a);
    if (lane == 0){ den[gw] = a; offq[gw] = off; }
}

// ---------------- attn = (phi(uq) @ ctxT^T)/den, fp16, dynamic smem ----------------
#define ATT_A (128*SH)              // halfs per A buffer
#define ATT_B (96*SH)               // halfs per B buffer
#define ATT_SMEM ((2*ATT_A + 2*ATT_B)*2)   // 64512 bytes
__global__ void __launch_bounds__(256, 2) attn_out_mma(
    const float* __restrict__ uq, const __half* __restrict__ ctxT,
    const float* __restrict__ den, const float* __restrict__ offq,
    __half* __restrict__ attn16)
{
    extern __shared__ __half smh[];
    __half* Asb[2] = { smh, smh + ATT_A };
    __half* Bsb[2] = { smh + 2*ATT_A, smh + 2*ATT_A + ATT_B };
    int tid = threadIdx.x, lane = tid & 31, wid = tid >> 5;
    int wm = wid & 3, wn = wid >> 2;  // n split 4 (32), e split 2 (48)
    int n0 = blockIdx.x*128, bh = blockIdx.y;
    int b = bh >> 3, h = bh & 7;
    const float* Ab = uq + ((size_t)bh*512 + n0)*256;
    const __half* Bb = ctxT + (size_t)bh*96*256;
    int lq = lane >> 2, lr = lane & 3;

    int fn = tid >> 1, fmg = (tid & 1)*32;
    float offr = offq[bh*512 + n0 + fn];
    float areg[32];
    auto loadA = [&](int c){
        const float* p = Ab + (size_t)fn*256 + c*64 + fmg;
        #pragma unroll
        for (int j = 0; j < 8; j++){
            float4 q = *(const float4*)(p + j*4);
            areg[j*4+0]=q.x; areg[j*4+1]=q.y; areg[j*4+2]=q.z; areg[j*4+3]=q.w;
        }
    };
    auto storeA = [&](int buf){
        __half* dst = Asb[buf] + fn*SH + fmg;
        #pragma unroll
        for (int j = 0; j < 16; j++){
            __half2 hv; hv.x = phih(areg[2*j], offr); hv.y = phih(areg[2*j+1], offr);
            *(__half2*)(dst + 2*j) = hv;
        }
    };
    auto issueB = [&](int c, int buf){
        uint32_t base = smem_u32(Bsb[buf]);
        #pragma unroll
        for (int i = 0; i < 3; i++){
            int p = tid + i*256; int r = p >> 3, cc = p & 7;
            CPA16(base + (uint32_t)(r*SH + cc*8)*2,
                  Bb + (size_t)r*256 + c*64 + cc*8);
        }
        asm volatile("cp.async.commit_group;");
    };

    float acc[2][6][4];
    #pragma unroll
    for (int mt = 0; mt < 2; mt++)
        #pragma unroll
        for (int nt = 0; nt < 6; nt++)
            #pragma unroll
            for (int r = 0; r < 4; r++) acc[mt][nt][r] = 0.f;

    issueB(0, 0); loadA(0); storeA(0);
    asm volatile("cp.async.wait_group 0;" ::: "memory");
    __syncthreads();

    int buf = 0;
    for (int c = 0; c < 4; c++){
        if (c < 3){ issueB(c + 1, buf ^ 1); loadA(c + 1); }

        #pragma unroll
        for (int ks = 0; ks < 4; ks++){
            int kb = ks*16 + 2*lr;
            uint32_t a[2][4], bfr[6][2];
            int ar = wm*32 + lq;
            #pragma unroll
            for (int mt = 0; mt < 2; mt++){
                const __half* p0 = Asb[buf] + (size_t)(ar + mt*16)*SH + kb;
                const __half* p1 = Asb[buf] + (size_t)(ar + mt*16 + 8)*SH + kb;
                a[mt][0] = LDH2(p0); a[mt][1] = LDH2(p1);
                a[mt][2] = LDH2(p0 + 8); a[mt][3] = LDH2(p1 + 8);
            }
            int ec = wn*48 + lq;
            #pragma unroll
            for (int nt = 0; nt < 6; nt++){
                const __half* p = Bsb[buf] + (size_t)(ec + nt*8)*SH + kb;
                bfr[nt][0] = LDH2(p); bfr[nt][1] = LDH2(p + 8);
            }
            #pragma unroll
            for (int mt = 0; mt < 2; mt++)
                #pragma unroll
                for (int nt = 0; nt < 6; nt++)
                    mma_f16(acc[mt][nt], a[mt], bfr[nt]);
        }
        __syncthreads();
        if (c < 3){
            storeA(buf ^ 1);
            asm volatile("cp.async.wait_group 0;" ::: "memory");
            __syncthreads();
            buf ^= 1;
        }
    }

    #pragma unroll
    for (int mt = 0; mt < 2; mt++){
        int n = n0 + wm*32 + mt*16 + lq;
        float d0 = 1.f/den[bh*512 + n];
        float d1 = 1.f/den[bh*512 + n + 8];
        __half* o0 = attn16 + (size_t)(b*512 + n)*768 + h*96;
        __half* o1 = attn16 + (size_t)(b*512 + n + 8)*768 + h*96;
        int e = wn*48 + lr*2;
        #pragma unroll
        for (int nt = 0; nt < 6; nt++){
            *(__half2*)(o0 + e + nt*8) = __floats2half2_rn(acc[mt][nt][0]*d0, acc[mt][nt][1]*d0);
            *(__half2*)(o1 + e + nt*8) = __floats2half2_rn(acc[mt][nt][2]*d1, acc[mt][nt][3]*d1);
        }
    }
}

// ---------------- prep kernels ----------------
__global__ void transpose_w(const float* __restrict__ src, __half* __restrict__ dst,
                            int K, int N)
{
    __shared__ float t[32][33];
    int n0 = blockIdx.x*32, k0 = blockIdx.y*32;
    size_t off = (size_t)blockIdx.z * (size_t)K * N;
    src += off; dst += off;
    int tx = threadIdx.x & 31, ty = threadIdx.x >> 5;
    #pragma unroll
    for (int i = 0; i < 32; i += 8)
        t[ty+i][tx] = src[(size_t)(k0+ty+i)*N + n0+tx];
    __syncthreads();
    #pragma unroll
    for (int i = 0; i < 32; i += 8)
        dst[(size_t)(n0+ty+i)*K + k0+tx] = __float2half_rn(t[tx][ty+i]);
}

__global__ void copy_round(const float* __restrict__ src, __half* __restrict__ dst){
    int i = blockIdx.x*256 + threadIdx.x;
    dst[i] = __float2half_rn(src[i]);
}

__global__ void proj_prep(const float* __restrict__ proj, __half* __restrict__ ph){
    int i = blockIdx.x*256 + threadIdx.x;   // 24576
    ph[i] = __float2half_rn(proj[i]*0.31947155f);
}

__global__ void im2col_kernel(const float* __restrict__ mel, __half* __restrict__ dst){
    int idx = blockIdx.x*256 + threadIdx.x;
    int pg = idx >> 8, k = idx & 255;
    int b = pg >> 9, p = pg & 511;
    int oh = p >> 3, ow = p & 7;
    int i = k >> 4, j = k & 15;
    dst[idx] = __float2half_rn(mel[(size_t)b*131072 + (size_t)(oh*16 + i)*128 + ow*16 + j]);
}

// ---------------- layernorm: fp32 in, fp16 out; resets g_kmax ----------------
__global__ void ln_kernel(const float* __restrict__ X, const float* __restrict__ sc,
                          const float* __restrict__ bb, __half* __restrict__ Y)
{
    __shared__ float s1[8], s2[8];
    int row = blockIdx.x, tid = threadIdx.x;
    if (row == 0 && tid == 0) g_kmax = 0u;
    int lane = tid & 31, wid = tid >> 5;
    const float* xr = X + (size_t)row*DMODEL;
    float v[3]; float sum = 0.f, sq = 0.f;
    #pragma unroll
    for (int i = 0; i < 3; i++){
        v[i] = xr[tid + 256*i];
        sum += v[i]; sq += v[i]*v[i];
    }
    sum = wsum(sum); sq = wsum(sq);
    if (lane == 0){ s1[wid] = sum; s2[wid] = sq; }
    __syncthreads();
    if (tid == 0){
        float a = 0.f, b2 = 0.f;
        #pragma unroll
        for (int i = 0; i < 8; i++){ a += s1[i]; b2 += s2[i]; }
        s1[0] = a; s2[0] = b2;
    }
    __syncthreads();
    float mean = s1[0]*(1.f/768.f);
    float var  = s2[0]*(1.f/768.f) - mean*mean;
    float rstd = rsqrtf(var + 1e-5f);
    __half* yr = Y + (size_t)row*DMODEL;
    #pragma unroll
    for (int i = 0; i < 3; i++){
        int d = tid + 256*i;
        yr[d] = __float2half_rn((v[i] - mean)*rstd*sc[d] + bb[d]);
    }
}

// ---------------- mask head ----------------
__global__ void mask_kernel(const float* __restrict__ X, const float* __restrict__ mw,
                            const float* __restrict__ mb, float* __restrict__ out)
{
    int row = blockIdx.x;
    int tid = threadIdx.x;
    int w = tid >> 5, lane = tid & 31;
    const float* xr = X + (size_t)row*768;
    float s = 0.f;
    for (int d = lane; d < 768; d += 32) s += xr[d]*mw[d*4 + w];
    s = wsum(s);
    if (lane == 0){
        float logit = s + mb[w];
        int b = row >> 9, n = row & 511;
        out[((size_t)b*4 + w)*512 + n] = 1.f/(1.f + expf(-logit));
    }
}

// ---------------- driver ----------------
extern "C" void kernel_launch(void* const* d_in, const int* in_sizes, int n_in,
                              void* d_out, int out_size)
{
    (void)in_sizes; (void)n_in; (void)out_size;
    const float* mel     = (const float*)d_in[0];
    const float* patch_w = (const float*)d_in[1];
    const float* patch_b = (const float*)d_in[2];
    const float* pos     = (const float*)d_in[3];
    const float* proj    = (const float*)d_in[4];
    const float* ln1_s   = (const float*)d_in[5];
    const float* ln1_b   = (const float*)d_in[6];
    const float* qkv_w   = (const float*)d_in[7];
    const float* qkv_b   = (const float*)d_in[8];
    const float* ao_w    = (const float*)d_in[9];
    const float* ao_b    = (const float*)d_in[10];
    const float* ln2_s   = (const float*)d_in[11];
    const float* ln2_b   = (const float*)d_in[12];
    const float* ff1_w   = (const float*)d_in[13];
    const float* ff1_b   = (const float*)d_in[14];
    const float* ff2_w   = (const float*)d_in[15];
    const float* ff2_b   = (const float*)d_in[16];
    const float* mask_w  = (const float*)d_in[17];
    const float* mask_b  = (const float*)d_in[18];
    float* out = (float*)d_out;

    float *x, *uq, *uk, *diag, *ps, *offq, *den;
    __half *lnb, *qkv, *ffb, *ctxb, *attn, *im2, *pwT, *projh;
    __half *wtq, *wtao, *wtf1, *wtf2;
    cudaGetSymbolAddress((void**)&x,    g_x);
    cudaGetSymbolAddress((void**)&lnb,  g_lnbuf);
    cudaGetSymbolAddress((void**)&qkv,  g_qkv);
    cudaGetSymbolAddress((void**)&ffb,  g_ffbuf);
    cudaGetSymbolAddress((void**)&uq,   g_uq);
    cudaGetSymbolAddress((void**)&uk,   g_uk);
    cudaGetSymbolAddress((void**)&ctxb, g_ctxb);
    cudaGetSymbolAddress((void**)&attn, g_attn);
    cudaGetSymbolAddress((void**)&diag, g_diag);
    cudaGetSymbolAddress((void**)&ps,   g_pksum);
    cudaGetSymbolAddress((void**)&offq, g_offq);
    cudaGetSymbolAddress((void**)&den,  g_den);
    cudaGetSymbolAddress((void**)&im2,  g_im2col);
    cudaGetSymbolAddress((void**)&pwT,  g_pwT);
    cudaGetSymbolAddress((void**)&projh,g_projh);
    cudaGetSymbolAddress((void**)&wtq,  g_wt_qkv);
    cudaGetSymbolAddress((void**)&wtao, g_wt_ao);
    cudaGetSymbolAddress((void**)&wtf1, g_wt_ff1);
    cudaGetSymbolAddress((void**)&wtf2, g_wt_ff2);

    cudaFuncSetAttribute(gemm_tc, cudaFuncAttributeMaxDynamicSharedMemorySize, GEMM_SMEM);
    cudaFuncSetAttribute(phi_u_mma, cudaFuncAttributeMaxDynamicSharedMemorySize, PHI_SMEM);
    cudaFuncSetAttribute(attn_out_mma, cudaFuncAttributeMaxDynamicSharedMemorySize, ATT_SMEM);

    // weight prep (fp16 [N][K])
    copy_round<<<768, 256>>>(patch_w, pwT);
    proj_prep<<<96, 256>>>(proj, projh);
    transpose_w<<<dim3(72, 24, 6), 256>>>(qkv_w, wtq, 768, 2304);
    transpose_w<<<dim3(24, 24, 6), 256>>>(ao_w,  wtao, 768, 768);
    transpose_w<<<dim3(96, 24, 6), 256>>>(ff1_w, wtf1, 768, 3072);
    transpose_w<<<dim3(24, 96, 6), 256>>>(ff2_w, wtf2, 3072, 768);

    // patch embed
    im2col_kernel<<<4096, 256>>>(mel, im2);
    gemm_tc<<<dim3(6, 32), 128, GEMM_SMEM>>>(im2, pwT, patch_b, x, 256, 768, 3, pos);

    for (int l = 0; l < NDEPTH; l++){
        ln_kernel<<<4096, 256>>>(x, ln1_s + l*768, ln1_b + l*768, lnb);
        gemm_tc<<<dim3(18, 32), 128, GEMM_SMEM>>>(
            lnb, wtq + (size_t)l*2304*768, qkv_b + l*2304, (float*)qkv, 768, 2304, 0, 0);
        phi_u_mma<<<dim3(2, 4, 128), 256, PHI_SMEM>>>(qkv, projh, uq, uk, diag);
        ctx_mma<<<dim3(4, 64), 256>>>(uk, qkv, diag, ctxb, ps);
        den_only<<<4096, 256>>>(uq, diag, ps, den, offq);
        attn_out_mma<<<dim3(4, 64), 256, ATT_SMEM>>>(uq, ctxb, den, offq, attn);
        gemm_tc<<<dim3(6, 32), 128, GEMM_SMEM>>>(
            attn, wtao + (size_t)l*768*768, ao_b + l*768, x, 768, 768, 2, 0);
        ln_kernel<<<4096, 256>>>(x, ln2_s + l*768, ln2_b + l*768, lnb);
        gemm_tc<<<dim3(24, 32), 128, GEMM_SMEM>>>(
            lnb, wtf1 + (size_t)l*768*3072, ff1_b + l*3072, (float*)ffb, 768, 3072, 1, 0);
        gemm_tc<<<dim3(6, 32), 128, GEMM_SMEM>>>(
            ffb, wtf2 + (size_t)l*3072*768, ff2_b + l*768, x, 3072, 768, 2, 0);
    }

    mask_kernel<<<4096, 128>>>(x, mask_w, mask_b, out);
}

// round 10
// speedup vs baseline: 1.5789x; 1.0072x over previous
#include <cuda_runtime.h>
#include <cuda_fp16.h>
#include <math.h>
#include <stdint.h>

#define TOK    4096
#define DMODEL 768
#define NSEQ   512
#define NHEAD  8
#define DHEAD  96
#define NFEAT  256
#define NBH    64
#define NFF    3072
#define NDEPTH 6

// ---------------- scratch ----------------
__device__ float  g_x[TOK*DMODEL];
__device__ __half g_lnbuf[TOK*DMODEL];
__device__ __half g_qkv[TOK*3*DMODEL];
__device__ __half g_ffbuf[TOK*NFF];
__device__ float  g_uq[NBH*NSEQ*NFEAT];
__device__ float  g_uk[NBH*NSEQ*NFEAT];
__device__ __half g_ctxb[NBH*DHEAD*NFEAT];   // ctxT [bh][96e][256m] fp16
__device__ __half g_attn[TOK*DMODEL];
__device__ float  g_diag[2*NBH*NSEQ];
__device__ float  g_pksum[NBH*NFEAT];
__device__ __half g_im2col[TOK*256];
__device__ __half g_pwT[DMODEL*256];
__device__ __half g_projh[NFEAT*DHEAD];      // fp16(proj * 96^-1/4)
__device__ unsigned g_kmax;
__device__ __half g_wt_qkv[NDEPTH*2304*768];
__device__ __half g_wt_ao [NDEPTH*768*768];
__device__ __half g_wt_ff1[NDEPTH*3072*768];
__device__ __half g_wt_ff2[NDEPTH*768*3072];

// ---------------- helpers ----------------
__device__ __forceinline__ unsigned enc_f(float f){
    unsigned u = __float_as_uint(f);
    return (u & 0x80000000u) ? ~u : (u | 0x80000000u);
}
__device__ __forceinline__ float dec_f(unsigned e){
    return (e & 0x80000000u) ? __uint_as_float(e ^ 0x80000000u) : __uint_as_float(~e);
}
__device__ __forceinline__ float wsum(float v){
    #pragma unroll
    for (int o = 16; o > 0; o >>= 1) v += __shfl_xor_sync(0xffffffffu, v, o);
    return v;
}
__device__ __forceinline__ float wmax(float v){
    #pragma unroll
    for (int o = 16; o > 0; o >>= 1) v = fmaxf(v, __shfl_xor_sync(0xffffffffu, v, o));
    return v;
}
__device__ __forceinline__ uint32_t smem_u32(const void* p){
    uint32_t a;
    asm("{ .reg .u64 t; cvta.to.shared.u64 t, %1; cvt.u32.u64 %0, t; }" : "=r"(a) : "l"(p));
    return a;
}
__device__ __forceinline__ void mma_f16(float* c, const uint32_t* a, const uint32_t* b){
    asm volatile(
        "mma.sync.aligned.m16n8k16.row.col.f32.f16.f16.f32 "
        "{%0,%1,%2,%3}, {%4,%5,%6,%7}, {%8,%9}, {%0,%1,%2,%3};"
        : "+f"(c[0]), "+f"(c[1]), "+f"(c[2]), "+f"(c[3])
        : "r"(a[0]), "r"(a[1]), "r"(a[2]), "r"(a[3]), "r"(b[0]), "r"(b[1]));
}
#define CPA16(saddr, gptr) \
    asm volatile("cp.async.cg.shared.global [%0], [%1], 16;" :: "r"(saddr), "l"(gptr))
__device__ __forceinline__ __half phih(float v, float off){
    return __float2half_rn((expf(v - off) + 1e-4f)*0.0625f);
}
#define LDH2(x) (*(const uint32_t*)(x))

// ---------------- fp16 mma GEMM: C[4096,N] = A @ WT^T, BK=64, 3-stage, 2 CTA/SM ----
#define SH 72                       // half stride per row
#define STAGEH (2*128*SH)           // halfs per stage
#define GEMM_SMEM (3*STAGEH*2)      // bytes = 110592
__global__ void __launch_bounds__(128, 2) gemm_tc(
    const __half* __restrict__ A, const __half* __restrict__ WT,
    const float* __restrict__ bias, float* __restrict__ C,
    int K, int Ncols, int ep, const float* __restrict__ aux)
{
    extern __shared__ __half smh[];
    int tid = threadIdx.x, lane = tid & 31, wid = tid >> 5;
    int wm = wid & 1, wn = wid >> 1;
    int n0 = blockIdx.x*128, m0 = blockIdx.y*128;
    int NC = K >> 6;
    uint32_t sb = smem_u32(smh);

    auto ldstage = [&](int s, int c){
        uint32_t abase = sb + (uint32_t)s*STAGEH*2;
        const __half* Ag = A  + (size_t)m0*K + c*64;
        const __half* Bg = WT + (size_t)n0*K + c*64;
        #pragma unroll
        for (int i = 0; i < 8; i++){
            int p = tid + i*128; int r = p >> 3, c8 = p & 7;
            CPA16(abase + (uint32_t)(r*SH + c8*8)*2, Ag + (size_t)r*K + c8*8);
        }
        #pragma unroll
        for (int i = 0; i < 8; i++){
            int p = tid + i*128; int r = p >> 3, c8 = p & 7;
            CPA16(abase + (uint32_t)(128*SH + r*SH + c8*8)*2, Bg + (size_t)r*K + c8*8);
        }
        asm volatile("cp.async.commit_group;");
    };

    float acc[4][8][4];
    #pragma unroll
    for (int mt = 0; mt < 4; mt++)
        #pragma unroll
        for (int nt = 0; nt < 8; nt++)
            #pragma unroll
            for (int r = 0; r < 4; r++) acc[mt][nt][r] = 0.f;

    ldstage(0, 0); ldstage(1, 1); ldstage(2, 2);
    int lq = lane >> 2, lr = lane & 3;

    for (int c = 0; c < NC; c++){
        int pend = NC - 1 - c;
        if (pend >= 2)      asm volatile("cp.async.wait_group 2;" ::: "memory");
        else if (pend == 1) asm volatile("cp.async.wait_group 1;" ::: "memory");
        else                asm volatile("cp.async.wait_group 0;" ::: "memory");
        __syncthreads();

        const __half* As = smh + (c % 3)*STAGEH;
        const __half* Bs = As + 128*SH;

        #pragma unroll
        for (int ks = 0; ks < 4; ks++){
            int kb = ks*16 + 2*lr;
            uint32_t a[4][4], b[8][2];
            int ar = wm*64 + lq;
            #pragma unroll
            for (int mt = 0; mt < 4; mt++){
                const __half* p0 = As + (size_t)(ar + mt*16)*SH + kb;
                const __half* p1 = As + (size_t)(ar + mt*16 + 8)*SH + kb;
                a[mt][0] = LDH2(p0); a[mt][1] = LDH2(p1);
                a[mt][2] = LDH2(p0 + 8); a[mt][3] = LDH2(p1 + 8);
            }
            int br = wn*64 + lq;
            #pragma unroll
            for (int nt = 0; nt < 8; nt++){
                const __half* p = Bs + (size_t)(br + nt*8)*SH + kb;
                b[nt][0] = LDH2(p); b[nt][1] = LDH2(p + 8);
            }
            #pragma unroll
            for (int mt = 0; mt < 4; mt++)
                #pragma unroll
                for (int nt = 0; nt < 8; nt++)
                    mma_f16(acc[mt][nt], a[mt], b[nt]);
        }
        __syncthreads();
        if (c + 3 < NC) ldstage(c % 3, c + 3);
    }

    int row_base = m0 + wm*64 + lq;
    int col_base = n0 + wn*64 + lr*2;
    __half* C16 = (__half*)C;
    #pragma unroll
    for (int mt = 0; mt < 4; mt++){
        #pragma unroll
        for (int h = 0; h < 2; h++){
            int row = row_base + mt*16 + h*8;
            const float* arow = aux ? (aux + (size_t)(row & 511)*DMODEL) : (const float*)0;
            #pragma unroll
            for (int nt = 0; nt < 8; nt++){
                int col = col_base + nt*8;
                float v0 = acc[mt][nt][h*2+0] + bias[col];
                float v1 = acc[mt][nt][h*2+1] + bias[col+1];
                if (ep == 0){
                    *(__half2*)(C16 + (size_t)row*Ncols + col) = __floats2half2_rn(v0, v1);
                } else if (ep == 1){
                    v0 = 0.5f*v0*(1.0f + erff(v0*0.70710678118654752f));
                    v1 = 0.5f*v1*(1.0f + erff(v1*0.70710678118654752f));
                    *(__half2*)(C16 + (size_t)row*Ncols + col) = __floats2half2_rn(v0, v1);
                } else {
                    float* crow = C + (size_t)row*Ncols;
                    if (ep == 2){
                        float2 old = *(const float2*)(crow + col);
                        v0 += old.x; v1 += old.y;
                    } else {
                        v0 += arow[col]; v1 += arow[col+1];
                    }
                    float2 o; o.x = v0; o.y = v1;
                    *(float2*)(crow + col) = o;
                }
            }
        }
    }
}

// ---------------- phi_u (q+k) fp16 mma, K=96, single-shot smem, fused diag ----------
#define PSH 104
#define PHI_SMEM (2*128*PSH*2)
__global__ void __launch_bounds__(256, 2) phi_u_mma(
    const __half* __restrict__ qkv16, const __half* __restrict__ projh,
    float* __restrict__ uq, float* __restrict__ uk, float* __restrict__ diag)
{
    extern __shared__ __half smh[];
    __shared__ float red[8];
    int tid = threadIdx.x, lane = tid & 31, wid = tid >> 5;
    int wm = wid & 3, wn = wid >> 2;
    int m0 = blockIdx.x*128, n0 = blockIdx.y*128;
    int zz = blockIdx.z;
    int bh = zz & 63, isk = zz >> 6;
    int b = bh >> 3, h = bh & 7;
    float* U = isk ? uk : uq;
    const __half* Ab = qkv16 + (size_t)(b*512 + n0)*2304 + isk*768 + h*96;
    const __half* Bb = projh + (size_t)m0*96;
    int lq = lane >> 2, lr = lane & 3;
    uint32_t sb = smem_u32(smh);

    // 128 rows x 96 halfs = 1536 16B chunks per operand
    #pragma unroll
    for (int i = 0; i < 6; i++){
        int p = tid + i*256; int r = p/12, cc = p - r*12;
        CPA16(sb + (uint32_t)(r*PSH + cc*8)*2, Ab + (size_t)r*2304 + cc*8);
    }
    #pragma unroll
    for (int i = 0; i < 6; i++){
        int p = tid + i*256; int r = p/12, cc = p - r*12;
        CPA16(sb + (uint32_t)(128*PSH + r*PSH + cc*8)*2, Bb + (size_t)r*96 + cc*8);
    }
    asm volatile("cp.async.commit_group;");
    asm volatile("cp.async.wait_group 0;" ::: "memory");
    __syncthreads();

    const __half* As = smh;
    const __half* Bs = smh + 128*PSH;

    float acc[2][8][4];
    #pragma unroll
    for (int mt = 0; mt < 2; mt++)
        #pragma unroll
        for (int nt = 0; nt < 8; nt++)
            #pragma unroll
            for (int r = 0; r < 4; r++) acc[mt][nt][r] = 0.f;

    #pragma unroll
    for (int ks = 0; ks < 6; ks++){
        int kb = ks*16 + 2*lr;
        uint32_t a[2][4], b[8][2];
        int ar = wm*32 + lq;
        #pragma unroll
        for (int mt = 0; mt < 2; mt++){
            const __half* p0 = As + (size_t)(ar + mt*16)*PSH + kb;
            const __half* p1 = As + (size_t)(ar + mt*16 + 8)*PSH + kb;
            a[mt][0] = LDH2(p0); a[mt][1] = LDH2(p1);
            a[mt][2] = LDH2(p0 + 8); a[mt][3] = LDH2(p1 + 8);
        }
        int bc = wn*64 + lq;
        #pragma unroll
        for (int nt = 0; nt < 8; nt++){
            const __half* p = Bs + (size_t)(bc + nt*8)*PSH + kb;
            b[nt][0] = LDH2(p); b[nt][1] = LDH2(p + 8);
        }
        #pragma unroll
        for (int mt = 0; mt < 2; mt++)
            #pragma unroll
            for (int nt = 0; nt < 8; nt++)
                mma_f16(acc[mt][nt], a[mt], b[nt]);
    }

    float tmax = -1e30f;
    #pragma unroll
    for (int mt = 0; mt < 2; mt++){
        int n = n0 + wm*32 + mt*16 + lq;
        int m = m0 + wn*64 + lr*2;
        float* u0 = U + ((size_t)bh*512 + n)*256;
        float* u1 = U + ((size_t)bh*512 + n + 8)*256;
        #pragma unroll
        for (int nt = 0; nt < 8; nt++){
            float v0 = acc[mt][nt][0], v1 = acc[mt][nt][1];
            float v2 = acc[mt][nt][2], v3 = acc[mt][nt][3];
            float2 p0; p0.x = v0; p0.y = v1;
            float2 p1; p1.x = v2; p1.y = v3;
            *(float2*)(u0 + m + nt*8) = p0;
            *(float2*)(u1 + m + nt*8) = p1;
            tmax = fmaxf(tmax, fmaxf(fmaxf(v0, v1), fmaxf(v2, v3)));
        }
    }

    if (blockIdx.x == 0 && tid < 128){
        float s = 0.f;
        const __half* xr = As + (size_t)tid*PSH;
        #pragma unroll
        for (int k = 0; k < 48; k++){
            __half2 hv = *(const __half2*)(xr + 2*k);
            float f0 = __low2float(hv), f1 = __high2float(hv);
            s += f0*f0 + f1*f1;
        }
        diag[isk*32768 + bh*512 + n0 + tid] = 0.05103103631f * s;
    }

    if (isk){
        tmax = wmax(tmax);
        if (lane == 0) red[wid] = tmax;
        __syncthreads();
        if (tid == 0){
            float m = red[0];
            #pragma unroll
            for (int i = 1; i < 8; i++) m = fmaxf(m, red[i]);
            atomicMax(&g_kmax, enc_f(m));
        }
    }
}

// ---------------- ctxT[e][m] = sum_n V[n][e]*pk[n][m], fp16, double-buffered -------
__global__ void __launch_bounds__(256, 2) ctx_mma(
    const float* __restrict__ uk, const __half* __restrict__ qkv16,
    const float* __restrict__ diag, __half* __restrict__ ctxT,
    float* __restrict__ ps)
{
    __shared__ __half VsT[2][96*40];     // [e][n]
    __shared__ __half PsT[2][64*40];     // [m][n]
    __shared__ float redc[256];
    int tid = threadIdx.x, lane = tid & 31, wid = tid >> 5;
    int wm = wid & 1, wn = wid >> 1;  // e split 2 (48), m split 4 (16)
    int m0 = blockIdx.x*64, bh = blockIdx.y;
    int b = bh >> 3, h = bh & 7;
    const __half* Vb = qkv16 + (size_t)(b*512)*2304 + 1536 + h*96;
    const float* Pb = uk + (size_t)(bh*512)*256 + m0;
    const float* dgk = diag + 32768 + bh*512;
    float kst = dec_f(g_kmax);
    int lq = lane >> 2, lr = lane & 3;

    int fn = tid >> 3;            // n within chunk (0..31)
    int fe = (tid & 7)*12;        // e start
    int fm = (tid & 7)*8;         // m start

    uint32_t vreg[6]; float preg[8]; float off = 0.f;
    auto loadRegs = [&](int c){
        const uint32_t* vp = (const uint32_t*)(Vb + (size_t)(c*32 + fn)*2304 + fe);
        #pragma unroll
        for (int j = 0; j < 6; j++) vreg[j] = vp[j];
        const float* pr = Pb + (size_t)(c*32 + fn)*256 + fm;
        float4 q0 = *(const float4*)pr, q1 = *(const float4*)(pr + 4);
        preg[0]=q0.x; preg[1]=q0.y; preg[2]=q0.z; preg[3]=q0.w;
        preg[4]=q1.x; preg[5]=q1.y; preg[6]=q1.z; preg[7]=q1.w;
        off = dgk[c*32 + fn] + kst;
    };
    auto storeSmem = [&](int buf){
        #pragma unroll
        for (int j = 0; j < 6; j++){
            __half2 hv = *reinterpret_cast<__half2*>(&vreg[j]);
            VsT[buf][(fe + 2*j)*40 + fn]     = __low2half(hv);
            VsT[buf][(fe + 2*j + 1)*40 + fn] = __high2half(hv);
        }
        #pragma unroll
        for (int j = 0; j < 8; j++)
            PsT[buf][(fm + j)*40 + fn] = phih(preg[j], off);
    };

    float acc[3][2][4];
    #pragma unroll
    for (int mt = 0; mt < 3; mt++)
        #pragma unroll
        for (int nt = 0; nt < 2; nt++)
            #pragma unroll
            for (int r = 0; r < 4; r++) acc[mt][nt][r] = 0.f;

    loadRegs(0);
    storeSmem(0);
    __syncthreads();

    int csm = tid & 63, csp = tid >> 6;
    float colsum = 0.f;
    int buf = 0;

    for (int c = 0; c < 16; c++){
        if (c < 15){ loadRegs(c + 1); storeSmem(buf ^ 1); }

        #pragma unroll
        for (int ks = 0; ks < 2; ks++){
            int kb = ks*16 + 2*lr;
            uint32_t a[3][4], bfr[2][2];
            int er = wm*48 + lq;
            #pragma unroll
            for (int mt = 0; mt < 3; mt++){
                const __half* p0 = &VsT[buf][(er + mt*16)*40 + kb];
                const __half* p1 = &VsT[buf][(er + mt*16 + 8)*40 + kb];
                a[mt][0] = LDH2(p0); a[mt][1] = LDH2(p1);
                a[mt][2] = LDH2(p0 + 8); a[mt][3] = LDH2(p1 + 8);
            }
            int bm = wn*16 + lq;
            #pragma unroll
            for (int nt = 0; nt < 2; nt++){
                const __half* p = &PsT[buf][(bm + nt*8)*40 + kb];
                bfr[nt][0] = LDH2(p); bfr[nt][1] = LDH2(p + 8);
            }
            #pragma unroll
            for (int mt = 0; mt < 3; mt++)
                #pragma unroll
                for (int nt = 0; nt < 2; nt++)
                    mma_f16(acc[mt][nt], a[mt], bfr[nt]);
        }
        {
            const __half* p = &PsT[buf][csm*40 + csp*8];
            float s = 0.f;
            #pragma unroll
            for (int j = 0; j < 8; j++) s += __half2float(p[j]);
            colsum += s;
        }
        __syncthreads();
        buf ^= 1;
    }

    redc[tid] = colsum;
    __syncthreads();
    if (tid < 64)
        ps[bh*256 + m0 + tid] = redc[tid] + redc[tid+64] + redc[tid+128] + redc[tid+192];

    #pragma unroll
    for (int mt = 0; mt < 3; mt++){
        int e = wm*48 + mt*16 + lq;
        int m = m0 + wn*16 + lr*2;
        __half* c0 = ctxT + ((size_t)bh*96 + e)*256;
        __half* c1 = ctxT + ((size_t)bh*96 + e + 8)*256;
        #pragma unroll
        for (int nt = 0; nt < 2; nt++){
            *(__half2*)(c0 + m + nt*8) = __floats2half2_rn(acc[mt][nt][0], acc[mt][nt][1]);
            *(__half2*)(c1 + m + nt*8) = __floats2half2_rn(acc[mt][nt][2], acc[mt][nt][3]);
        }
    }
}

// ---------------- attn = (phi(uq) @ ctxT^T)/den, den fused in-kernel ----------------
#define ATT_A (128*SH)              // halfs per A buffer
#define ATT_B (96*SH)               // halfs per B buffer
#define ATT_SMEM ((2*ATT_A + 2*ATT_B)*2)   // 64512 bytes
__global__ void __launch_bounds__(256, 2) attn_out_mma(
    const float* __restrict__ uq, const __half* __restrict__ ctxT,
    const float* __restrict__ diagq, const float* __restrict__ ps,
    __half* __restrict__ attn16)
{
    extern __shared__ __half smh[];
    __half* Asb[2] = { smh, smh + ATT_A };
    __half* Bsb[2] = { smh + 2*ATT_A, smh + 2*ATT_A + ATT_B };
    __shared__ float denS[128];
    int tid = threadIdx.x, lane = tid & 31, wid = tid >> 5;
    int wm = wid & 3, wn = wid >> 2;  // n split 4 (32), e split 2 (48)
    int n0 = blockIdx.x*128, bh = blockIdx.y;
    int b = bh >> 3, h = bh & 7;
    const float* Ab = uq + ((size_t)bh*512 + n0)*256;
    const __half* Bb = ctxT + (size_t)bh*96*256;
    const float* psb = ps + bh*256;
    int lq = lane >> 2, lr = lane & 3;

    int fn = tid >> 1, fmg = (tid & 1)*32;
    float areg[32];
    auto loadA = [&](int c){
        const float* p = Ab + (size_t)fn*256 + c*64 + fmg;
        #pragma unroll
        for (int j = 0; j < 8; j++){
            float4 q = *(const float4*)(p + j*4);
            areg[j*4+0]=q.x; areg[j*4+1]=q.y; areg[j*4+2]=q.z; areg[j*4+3]=q.w;
        }
    };

    // phase 1: row max over all 256 m (pair of threads per row)
    float vmax = -1e30f;
    for (int c = 0; c < 4; c++){
        loadA(c);
        #pragma unroll
        for (int j = 0; j < 32; j++) vmax = fmaxf(vmax, areg[j]);
    }
    vmax = fmaxf(vmax, __shfl_xor_sync(0xffffffffu, vmax, 1));
    float offr = diagq[bh*512 + n0 + fn] + vmax;
    float sden = 0.f;

    auto storeA = [&](int buf, int c){
        __half* dst = Asb[buf] + fn*SH + fmg;
        const float* pp = psb + c*64 + fmg;
        #pragma unroll
        for (int j = 0; j < 16; j++){
            __half2 hv; hv.x = phih(areg[2*j], offr); hv.y = phih(areg[2*j+1], offr);
            *(__half2*)(dst + 2*j) = hv;
            sden += __half2float(hv.x)*pp[2*j] + __half2float(hv.y)*pp[2*j+1];
        }
    };
    auto issueB = [&](int c, int buf){
        uint32_t base = smem_u32(Bsb[buf]);
        #pragma unroll
        for (int i = 0; i < 3; i++){
            int p = tid + i*256; int r = p >> 3, cc = p & 7;
            CPA16(base + (uint32_t)(r*SH + cc*8)*2,
                  Bb + (size_t)r*256 + c*64 + cc*8);
        }
        asm volatile("cp.async.commit_group;");
    };

    float acc[2][6][4];
    #pragma unroll
    for (int mt = 0; mt < 2; mt++)
        #pragma unroll
        for (int nt = 0; nt < 6; nt++)
            #pragma unroll
            for (int r = 0; r < 4; r++) acc[mt][nt][r] = 0.f;

    issueB(0, 0); loadA(0); storeA(0, 0);
    asm volatile("cp.async.wait_group 0;" ::: "memory");
    __syncthreads();

    int buf = 0;
    for (int c = 0; c < 4; c++){
        if (c < 3){ issueB(c + 1, buf ^ 1); loadA(c + 1); }

        #pragma unroll
        for (int ks = 0; ks < 4; ks++){
            int kb = ks*16 + 2*lr;
            uint32_t a[2][4], bfr[6][2];
            int ar = wm*32 + lq;
            #pragma unroll
            for (int mt = 0; mt < 2; mt++){
                const __half* p0 = Asb[buf] + (size_t)(ar + mt*16)*SH + kb;
                const __half* p1 = Asb[buf] + (size_t)(ar + mt*16 + 8)*SH + kb;
                a[mt][0] = LDH2(p0); a[mt][1] = LDH2(p1);
                a[mt][2] = LDH2(p0 + 8); a[mt][3] = LDH2(p1 + 8);
            }
            int ec = wn*48 + lq;
            #pragma unroll
            for (int nt = 0; nt < 6; nt++){
                const __half* p = Bsb[buf] + (size_t)(ec + nt*8)*SH + kb;
                bfr[nt][0] = LDH2(p); bfr[nt][1] = LDH2(p + 8);
            }
            #pragma unroll
            for (int mt = 0; mt < 2; mt++)
                #pragma unroll
                for (int nt = 0; nt < 6; nt++)
                    mma_f16(acc[mt][nt], a[mt], bfr[nt]);
        }
        __syncthreads();
        if (c < 3){
            storeA(buf ^ 1, c + 1);
            asm volatile("cp.async.wait_group 0;" ::: "memory");
            __syncthreads();
            buf ^= 1;
        }
    }

    // combine den pair (even + odd thread of each row) and publish
    sden += __shfl_xor_sync(0xffffffffu, sden, 1);
    if ((tid & 1) == 0) denS[fn] = sden;
    __syncthreads();

    #pragma unroll
    for (int mt = 0; mt < 2; mt++){
        int nloc = wm*32 + mt*16 + lq;
        int n = n0 + nloc;
        float d0 = 1.f/denS[nloc];
        float d1 = 1.f/denS[nloc + 8];
        __half* o0 = attn16 + (size_t)(b*512 + n)*768 + h*96;
        __half* o1 = attn16 + (size_t)(b*512 + n + 8)*768 + h*96;
        int e = wn*48 + lr*2;
        #pragma unroll
        for (int nt = 0; nt < 6; nt++){
            *(__half2*)(o0 + e + nt*8) = __floats2half2_rn(acc[mt][nt][0]*d0, acc[mt][nt][1]*d0);
            *(__half2*)(o1 + e + nt*8) = __floats2half2_rn(acc[mt][nt][2]*d1, acc[mt][nt][3]*d1);
        }
    }
}

// ---------------- prep kernels ----------------
__global__ void transpose_w(const float* __restrict__ src, __half* __restrict__ dst,
                            int K, int N)
{
    __shared__ float t[32][33];
    int n0 = blockIdx.x*32, k0 = blockIdx.y*32;
    size_t off = (size_t)blockIdx.z * (size_t)K * N;
    src += off; dst += off;
    int tx = threadIdx.x & 31, ty = threadIdx.x >> 5;
    #pragma unroll
    for (int i = 0; i < 32; i += 8)
        t[ty+i][tx] = src[(size_t)(k0+ty+i)*N + n0+tx];
    __syncthreads();
    #pragma unroll
    for (int i = 0; i < 32; i += 8)
        dst[(size_t)(n0+ty+i)*K + k0+tx] = __float2half_rn(t[tx][ty+i]);
}

__global__ void copy_round(const float* __restrict__ src, __half* __restrict__ dst){
    int i = blockIdx.x*256 + threadIdx.x;
    dst[i] = __float2half_rn(src[i]);
}

__global__ void proj_prep(const float* __restrict__ proj, __half* __restrict__ ph){
    int i = blockIdx.x*256 + threadIdx.x;   // 24576
    ph[i] = __float2half_rn(proj[i]*0.31947155f);
}

__global__ void im2col_kernel(const float* __restrict__ mel, __half* __restrict__ dst){
    int idx = blockIdx.x*256 + threadIdx.x;
    int pg = idx >> 8, k = idx & 255;
    int b = pg >> 9, p = pg & 511;
    int oh = p >> 3, ow = p & 7;
    int i = k >> 4, j = k & 15;
    dst[idx] = __float2half_rn(mel[(size_t)b*131072 + (size_t)(oh*16 + i)*128 + ow*16 + j]);
}

// ---------------- layernorm: fp32 in, fp16 out; resets g_kmax ----------------
__global__ void ln_kernel(const float* __restrict__ X, const float* __restrict__ sc,
                          const float* __restrict__ bb, __half* __restrict__ Y)
{
    __shared__ float s1[8], s2[8];
    int row = blockIdx.x, tid = threadIdx.x;
    if (row == 0 && tid == 0) g_kmax = 0u;
    int lane = tid & 31, wid = tid >> 5;
    const float* xr = X + (size_t)row*DMODEL;
    float v[3]; float sum = 0.f, sq = 0.f;
    #pragma unroll
    for (int i = 0; i < 3; i++){
        v[i] = xr[tid + 256*i];
        sum += v[i]; sq += v[i]*v[i];
    }
    sum = wsum(sum); sq = wsum(sq);
    if (lane == 0){ s1[wid] = sum; s2[wid] = sq; }
    __syncthreads();
    if (tid == 0){
        float a = 0.f, b2 = 0.f;
        #pragma unroll
        for (int i = 0; i < 8; i++){ a += s1[i]; b2 += s2[i]; }
        s1[0] = a; s2[0] = b2;
    }
    __syncthreads();
    float mean = s1[0]*(1.f/768.f);
    float var  = s2[0]*(1.f/768.f) - mean*mean;
    float rstd = rsqrtf(var + 1e-5f);
    __half* yr = Y + (size_t)row*DMODEL;
    #pragma unroll
    for (int i = 0; i < 3; i++){
        int d = tid + 256*i;
        yr[d] = __float2half_rn((v[i] - mean)*rstd*sc[d] + bb[d]);
    }
}

// ---------------- mask head ----------------
__global__ void mask_kernel(const float* __restrict__ X, const float* __restrict__ mw,
                            const float* __restrict__ mb, float* __restrict__ out)
{
    int row = blockIdx.x;
    int tid = threadIdx.x;
    int w = tid >> 5, lane = tid & 31;
    const float* xr = X + (size_t)row*768;
    float s = 0.f;
    for (int d = lane; d < 768; d += 32) s += xr[d]*mw[d*4 + w];
    s = wsum(s);
    if (lane == 0){
        float logit = s + mb[w];
        int b = row >> 9, n = row & 511;
        out[((size_t)b*4 + w)*512 + n] = 1.f/(1.f + expf(-logit));
    }
}

// ---------------- driver ----------------
extern "C" void kernel_launch(void* const* d_in, const int* in_sizes, int n_in,
                              void* d_out, int out_size)
{
    (void)in_sizes; (void)n_in; (void)out_size;
    const float* mel     = (const float*)d_in[0];
    const float* patch_w = (const float*)d_in[1];
    const float* patch_b = (const float*)d_in[2];
    const float* pos     = (const float*)d_in[3];
    const float* proj    = (const float*)d_in[4];
    const float* ln1_s   = (const float*)d_in[5];
    const float* ln1_b   = (const float*)d_in[6];
    const float* qkv_w   = (const float*)d_in[7];
    const float* qkv_b   = (const float*)d_in[8];
    const float* ao_w    = (const float*)d_in[9];
    const float* ao_b    = (const float*)d_in[10];
    const float* ln2_s   = (const float*)d_in[11];
    const float* ln2_b   = (const float*)d_in[12];
    const float* ff1_w   = (const float*)d_in[13];
    const float* ff1_b   = (const float*)d_in[14];
    const float* ff2_w   = (const float*)d_in[15];
    const float* ff2_b   = (const float*)d_in[16];
    const float* mask_w  = (const float*)d_in[17];
    const float* mask_b  = (const float*)d_in[18];
    float* out = (float*)d_out;

    float *x, *uq, *uk, *diag, *ps;
    __half *lnb, *qkv, *ffb, *ctxb, *attn, *im2, *pwT, *projh;
    __half *wtq, *wtao, *wtf1, *wtf2;
    cudaGetSymbolAddress((void**)&x,    g_x);
    cudaGetSymbolAddress((void**)&lnb,  g_lnbuf);
    cudaGetSymbolAddress((void**)&qkv,  g_qkv);
    cudaGetSymbolAddress((void**)&ffb,  g_ffbuf);
    cudaGetSymbolAddress((void**)&uq,   g_uq);
    cudaGetSymbolAddress((void**)&uk,   g_uk);
    cudaGetSymbolAddress((void**)&ctxb, g_ctxb);
    cudaGetSymbolAddress((void**)&attn, g_attn);
    cudaGetSymbolAddress((void**)&diag, g_diag);
    cudaGetSymbolAddress((void**)&ps,   g_pksum);
    cudaGetSymbolAddress((void**)&im2,  g_im2col);
    cudaGetSymbolAddress((void**)&pwT,  g_pwT);
    cudaGetSymbolAddress((void**)&projh,g_projh);
    cudaGetSymbolAddress((void**)&wtq,  g_wt_qkv);
    cudaGetSymbolAddress((void**)&wtao, g_wt_ao);
    cudaGetSymbolAddress((void**)&wtf1, g_wt_ff1);
    cudaGetSymbolAddress((void**)&wtf2, g_wt_ff2);

    cudaFuncSetAttribute(gemm_tc, cudaFuncAttributeMaxDynamicSharedMemorySize, GEMM_SMEM);
    cudaFuncSetAttribute(phi_u_mma, cudaFuncAttributeMaxDynamicSharedMemorySize, PHI_SMEM);
    cudaFuncSetAttribute(attn_out_mma, cudaFuncAttributeMaxDynamicSharedMemorySize, ATT_SMEM);

    // weight prep (fp16 [N][K])
    copy_round<<<768, 256>>>(patch_w, pwT);
    proj_prep<<<96, 256>>>(proj, projh);
    transpose_w<<<dim3(72, 24, 6), 256>>>(qkv_w, wtq, 768, 2304);
    transpose_w<<<dim3(24, 24, 6), 256>>>(ao_w,  wtao, 768, 768);
    transpose_w<<<dim3(96, 24, 6), 256>>>(ff1_w, wtf1, 768, 3072);
    transpose_w<<<dim3(24, 96, 6), 256>>>(ff2_w, wtf2, 3072, 768);

    // patch embed
    im2col_kernel<<<4096, 256>>>(mel, im2);
    gemm_tc<<<dim3(6, 32), 128, GEMM_SMEM>>>(im2, pwT, patch_b, x, 256, 768, 3, pos);

    for (int l = 0; l < NDEPTH; l++){
        ln_kernel<<<4096, 256>>>(x, ln1_s + l*768, ln1_b + l*768, lnb);
        gemm_tc<<<dim3(18, 32), 128, GEMM_SMEM>>>(
            lnb, wtq + (size_t)l*2304*768, qkv_b + l*2304, (float*)qkv, 768, 2304, 0, 0);
        phi_u_mma<<<dim3(2, 4, 128), 256, PHI_SMEM>>>(qkv, projh, uq, uk, diag);
        ctx_mma<<<dim3(4, 64), 256>>>(uk, qkv, diag, ctxb, ps);
        attn_out_mma<<<dim3(4, 64), 256, ATT_SMEM>>>(uq, ctxb, diag, ps, attn);
        gemm_tc<<<dim3(6, 32), 128, GEMM_SMEM>>>(
            attn, wtao + (size_t)l*768*768, ao_b + l*768, x, 768, 768, 2, 0);
        ln_kernel<<<4096, 256>>>(x, ln2_s + l*768, ln2_b + l*768, lnb);
        gemm_tc<<<dim3(24, 32), 128, GEMM_SMEM>>>(
            lnb, wtf1 + (size_t)l*768*3072, ff1_b + l*3072, (float*)ffb, 768, 3072, 1, 0);
        gemm_tc<<<dim3(6, 32), 128, GEMM_SMEM>>>(
            ffb, wtf2 + (size_t)l*3072*768, ff2_b + l*768, x, 3072, 768, 2, 0);
    }

    mask_kernel<<<4096, 128>>>(x, mask_w, mask_b, out);
}

// round 11
// speedup vs baseline: 1.5965x; 1.0112x over previous
#include <cuda_runtime.h>
#include <cuda_fp16.h>
#include <math.h>
#include <stdint.h>

#define TOK    4096
#define DMODEL 768
#define NSEQ   512
#define NHEAD  8
#define DHEAD  96
#define NFEAT  256
#define NBH    64
#define NFF    3072
#define NDEPTH 6

// ---------------- scratch ----------------
__device__ float  g_x[TOK*DMODEL];
__device__ __half g_lnbuf[TOK*DMODEL];
__device__ __half g_qkv[TOK*3*DMODEL];
__device__ __half g_ffbuf[TOK*NFF];
__device__ float  g_uq[NBH*NSEQ*NFEAT];
__device__ float  g_uk[NBH*NSEQ*NFEAT];
__device__ __half g_ctxb[NBH*DHEAD*NFEAT];   // ctxT [bh][96e][256m] fp16
__device__ __half g_attn[TOK*DMODEL];
__device__ float  g_diag[2*NBH*NSEQ];
__device__ float  g_pksum[NBH*NFEAT];
__device__ float  g_pqmax[2*NBH*NSEQ];       // per-mtile rowmax of u_q
__device__ __half g_im2col[TOK*256];
__device__ __half g_pwT[DMODEL*256];
__device__ __half g_projh[NFEAT*DHEAD];      // fp16(proj * 96^-1/4)
__device__ unsigned g_kmax;
__device__ __half g_wt_qkv[NDEPTH*2304*768];
__device__ __half g_wt_ao [NDEPTH*768*768];
__device__ __half g_wt_ff1[NDEPTH*3072*768];
__device__ __half g_wt_ff2[NDEPTH*768*3072];

// ---------------- helpers ----------------
__device__ __forceinline__ unsigned enc_f(float f){
    unsigned u = __float_as_uint(f);
    return (u & 0x80000000u) ? ~u : (u | 0x80000000u);
}
__device__ __forceinline__ float dec_f(unsigned e){
    return (e & 0x80000000u) ? __uint_as_float(e ^ 0x80000000u) : __uint_as_float(~e);
}
__device__ __forceinline__ float wsum(float v){
    #pragma unroll
    for (int o = 16; o > 0; o >>= 1) v += __shfl_xor_sync(0xffffffffu, v, o);
    return v;
}
__device__ __forceinline__ float wmax(float v){
    #pragma unroll
    for (int o = 16; o > 0; o >>= 1) v = fmaxf(v, __shfl_xor_sync(0xffffffffu, v, o));
    return v;
}
__device__ __forceinline__ uint32_t smem_u32(const void* p){
    uint32_t a;
    asm("{ .reg .u64 t; cvta.to.shared.u64 t, %1; cvt.u32.u64 %0, t; }" : "=r"(a) : "l"(p));
    return a;
}
__device__ __forceinline__ void mma_f16(float* c, const uint32_t* a, const uint32_t* b){
    asm volatile(
        "mma.sync.aligned.m16n8k16.row.col.f32.f16.f16.f32 "
        "{%0,%1,%2,%3}, {%4,%5,%6,%7}, {%8,%9}, {%0,%1,%2,%3};"
        : "+f"(c[0]), "+f"(c[1]), "+f"(c[2]), "+f"(c[3])
        : "r"(a[0]), "r"(a[1]), "r"(a[2]), "r"(a[3]), "r"(b[0]), "r"(b[1]));
}
#define CPA16(saddr, gptr) \
    asm volatile("cp.async.cg.shared.global [%0], [%1], 16;" :: "r"(saddr), "l"(gptr))
__device__ __forceinline__ __half phih(float v, float off){
    return __float2half_rn((expf(v - off) + 1e-4f)*0.0625f);
}
#define LDH2(x) (*(const uint32_t*)(x))

// ---------------- fp16 mma GEMM: C[4096,N] = A @ WT^T, BK=64, 3-stage, 2 CTA/SM ----
#define SH 72                       // half stride per row
#define STAGEH (2*128*SH)           // halfs per stage
#define GEMM_SMEM (3*STAGEH*2)      // bytes = 110592
__global__ void __launch_bounds__(128, 2) gemm_tc(
    const __half* __restrict__ A, const __half* __restrict__ WT,
    const float* __restrict__ bias, float* __restrict__ C,
    int K, int Ncols, int ep, const float* __restrict__ aux)
{
    extern __shared__ __half smh[];
    int tid = threadIdx.x, lane = tid & 31, wid = tid >> 5;
    int wm = wid & 1, wn = wid >> 1;
    int n0 = blockIdx.x*128, m0 = blockIdx.y*128;
    int NC = K >> 6;
    uint32_t sb = smem_u32(smh);

    auto ldstage = [&](int s, int c){
        uint32_t abase = sb + (uint32_t)s*STAGEH*2;
        const __half* Ag = A  + (size_t)m0*K + c*64;
        const __half* Bg = WT + (size_t)n0*K + c*64;
        #pragma unroll
        for (int i = 0; i < 8; i++){
            int p = tid + i*128; int r = p >> 3, c8 = p & 7;
            CPA16(abase + (uint32_t)(r*SH + c8*8)*2, Ag + (size_t)r*K + c8*8);
        }
        #pragma unroll
        for (int i = 0; i < 8; i++){
            int p = tid + i*128; int r = p >> 3, c8 = p & 7;
            CPA16(abase + (uint32_t)(128*SH + r*SH + c8*8)*2, Bg + (size_t)r*K + c8*8);
        }
        asm volatile("cp.async.commit_group;");
    };

    float acc[4][8][4];
    #pragma unroll
    for (int mt = 0; mt < 4; mt++)
        #pragma unroll
        for (int nt = 0; nt < 8; nt++)
            #pragma unroll
            for (int r = 0; r < 4; r++) acc[mt][nt][r] = 0.f;

    ldstage(0, 0); ldstage(1, 1); ldstage(2, 2);
    int lq = lane >> 2, lr = lane & 3;

    for (int c = 0; c < NC; c++){
        int pend = NC - 1 - c;
        if (pend >= 2)      asm volatile("cp.async.wait_group 2;" ::: "memory");
        else if (pend == 1) asm volatile("cp.async.wait_group 1;" ::: "memory");
        else                asm volatile("cp.async.wait_group 0;" ::: "memory");
        __syncthreads();

        const __half* As = smh + (c % 3)*STAGEH;
        const __half* Bs = As + 128*SH;

        #pragma unroll
        for (int ks = 0; ks < 4; ks++){
            int kb = ks*16 + 2*lr;
            uint32_t a[4][4], b[8][2];
            int ar = wm*64 + lq;
            #pragma unroll
            for (int mt = 0; mt < 4; mt++){
                const __half* p0 = As + (size_t)(ar + mt*16)*SH + kb;
                const __half* p1 = As + (size_t)(ar + mt*16 + 8)*SH + kb;
                a[mt][0] = LDH2(p0); a[mt][1] = LDH2(p1);
                a[mt][2] = LDH2(p0 + 8); a[mt][3] = LDH2(p1 + 8);
            }
            int br = wn*64 + lq;
            #pragma unroll
            for (int nt = 0; nt < 8; nt++){
                const __half* p = Bs + (size_t)(br + nt*8)*SH + kb;
                b[nt][0] = LDH2(p); b[nt][1] = LDH2(p + 8);
            }
            #pragma unroll
            for (int mt = 0; mt < 4; mt++)
                #pragma unroll
                for (int nt = 0; nt < 8; nt++)
                    mma_f16(acc[mt][nt], a[mt], b[nt]);
        }
        __syncthreads();
        if (c + 3 < NC) ldstage(c % 3, c + 3);
    }

    int row_base = m0 + wm*64 + lq;
    int col_base = n0 + wn*64 + lr*2;
    __half* C16 = (__half*)C;
    #pragma unroll
    for (int mt = 0; mt < 4; mt++){
        #pragma unroll
        for (int h = 0; h < 2; h++){
            int row = row_base + mt*16 + h*8;
            const float* arow = aux ? (aux + (size_t)(row & 511)*DMODEL) : (const float*)0;
            #pragma unroll
            for (int nt = 0; nt < 8; nt++){
                int col = col_base + nt*8;
                float v0 = acc[mt][nt][h*2+0] + bias[col];
                float v1 = acc[mt][nt][h*2+1] + bias[col+1];
                if (ep == 0){
                    *(__half2*)(C16 + (size_t)row*Ncols + col) = __floats2half2_rn(v0, v1);
                } else if (ep == 1){
                    v0 = 0.5f*v0*(1.0f + erff(v0*0.70710678118654752f));
                    v1 = 0.5f*v1*(1.0f + erff(v1*0.70710678118654752f));
                    *(__half2*)(C16 + (size_t)row*Ncols + col) = __floats2half2_rn(v0, v1);
                } else {
                    float* crow = C + (size_t)row*Ncols;
                    if (ep == 2){
                        float2 old = *(const float2*)(crow + col);
                        v0 += old.x; v1 += old.y;
                    } else {
                        v0 += arow[col]; v1 += arow[col+1];
                    }
                    float2 o; o.x = v0; o.y = v1;
                    *(float2*)(crow + col) = o;
                }
            }
        }
    }
}

// ---------------- phi_u (q+k) fp16 mma, K=96, fused diag + rowmax/globalmax --------
#define PSH 104
#define PHI_SMEM (2*128*PSH*2)
__global__ void __launch_bounds__(256, 2) phi_u_mma(
    const __half* __restrict__ qkv16, const __half* __restrict__ projh,
    float* __restrict__ uq, float* __restrict__ uk, float* __restrict__ diag,
    float* __restrict__ pqmax)
{
    extern __shared__ __half smh[];
    __shared__ float red[8];
    __shared__ float pm[2][128];
    int tid = threadIdx.x, lane = tid & 31, wid = tid >> 5;
    int wm = wid & 3, wn = wid >> 2;
    int m0 = blockIdx.x*128, n0 = blockIdx.y*128;
    int zz = blockIdx.z;
    int bh = zz & 63, isk = zz >> 6;
    int b = bh >> 3, h = bh & 7;
    float* U = isk ? uk : uq;
    const __half* Ab = qkv16 + (size_t)(b*512 + n0)*2304 + isk*768 + h*96;
    const __half* Bb = projh + (size_t)m0*96;
    int lq = lane >> 2, lr = lane & 3;
    uint32_t sb = smem_u32(smh);

    // 128 rows x 96 halfs = 1536 16B chunks per operand
    #pragma unroll
    for (int i = 0; i < 6; i++){
        int p = tid + i*256; int r = p/12, cc = p - r*12;
        CPA16(sb + (uint32_t)(r*PSH + cc*8)*2, Ab + (size_t)r*2304 + cc*8);
    }
    #pragma unroll
    for (int i = 0; i < 6; i++){
        int p = tid + i*256; int r = p/12, cc = p - r*12;
        CPA16(sb + (uint32_t)(128*PSH + r*PSH + cc*8)*2, Bb + (size_t)r*96 + cc*8);
    }
    asm volatile("cp.async.commit_group;");
    asm volatile("cp.async.wait_group 0;" ::: "memory");
    __syncthreads();

    const __half* As = smh;
    const __half* Bs = smh + 128*PSH;

    float acc[2][8][4];
    #pragma unroll
    for (int mt = 0; mt < 2; mt++)
        #pragma unroll
        for (int nt = 0; nt < 8; nt++)
            #pragma unroll
            for (int r = 0; r < 4; r++) acc[mt][nt][r] = 0.f;

    #pragma unroll
    for (int ks = 0; ks < 6; ks++){
        int kb = ks*16 + 2*lr;
        uint32_t a[2][4], b[8][2];
        int ar = wm*32 + lq;
        #pragma unroll
        for (int mt = 0; mt < 2; mt++){
            const __half* p0 = As + (size_t)(ar + mt*16)*PSH + kb;
            const __half* p1 = As + (size_t)(ar + mt*16 + 8)*PSH + kb;
            a[mt][0] = LDH2(p0); a[mt][1] = LDH2(p1);
            a[mt][2] = LDH2(p0 + 8); a[mt][3] = LDH2(p1 + 8);
        }
        int bc = wn*64 + lq;
        #pragma unroll
        for (int nt = 0; nt < 8; nt++){
            const __half* p = Bs + (size_t)(bc + nt*8)*PSH + kb;
            b[nt][0] = LDH2(p); b[nt][1] = LDH2(p + 8);
        }
        #pragma unroll
        for (int mt = 0; mt < 2; mt++)
            #pragma unroll
            for (int nt = 0; nt < 8; nt++)
                mma_f16(acc[mt][nt], a[mt], b[nt]);
    }

    float rmx[2][2] = {{-1e30f, -1e30f}, {-1e30f, -1e30f}};
    #pragma unroll
    for (int mt = 0; mt < 2; mt++){
        int n = n0 + wm*32 + mt*16 + lq;
        int m = m0 + wn*64 + lr*2;
        float* u0 = U + ((size_t)bh*512 + n)*256;
        float* u1 = U + ((size_t)bh*512 + n + 8)*256;
        #pragma unroll
        for (int nt = 0; nt < 8; nt++){
            float v0 = acc[mt][nt][0], v1 = acc[mt][nt][1];
            float v2 = acc[mt][nt][2], v3 = acc[mt][nt][3];
            float2 p0; p0.x = v0; p0.y = v1;
            float2 p1; p1.x = v2; p1.y = v3;
            *(float2*)(u0 + m + nt*8) = p0;
            *(float2*)(u1 + m + nt*8) = p1;
            rmx[mt][0] = fmaxf(rmx[mt][0], fmaxf(v0, v1));
            rmx[mt][1] = fmaxf(rmx[mt][1], fmaxf(v2, v3));
        }
    }

    if (blockIdx.x == 0 && tid < 128){
        float s = 0.f;
        const __half* xr = As + (size_t)tid*PSH;
        #pragma unroll
        for (int k = 0; k < 48; k++){
            __half2 hv = *(const __half2*)(xr + 2*k);
            float f0 = __low2float(hv), f1 = __high2float(hv);
            s += f0*f0 + f1*f1;
        }
        diag[isk*32768 + bh*512 + n0 + tid] = 0.05103103631f * s;
    }

    if (isk){
        float tmax = fmaxf(fmaxf(rmx[0][0], rmx[0][1]), fmaxf(rmx[1][0], rmx[1][1]));
        tmax = wmax(tmax);
        if (lane == 0) red[wid] = tmax;
        __syncthreads();
        if (tid == 0){
            float m = red[0];
            #pragma unroll
            for (int i = 1; i < 8; i++) m = fmaxf(m, red[i]);
            atomicMax(&g_kmax, enc_f(m));
        }
    } else {
        // per-row max over this m-tile: reduce lr group, combine wn halves
        #pragma unroll
        for (int mt = 0; mt < 2; mt++)
            #pragma unroll
            for (int hh = 0; hh < 2; hh++){
                float v = rmx[mt][hh];
                v = fmaxf(v, __shfl_xor_sync(0xffffffffu, v, 1));
                v = fmaxf(v, __shfl_xor_sync(0xffffffffu, v, 2));
                if (lr == 0) pm[wn][wm*32 + mt*16 + hh*8 + lq] = v;
            }
        __syncthreads();
        if (tid < 128)
            pqmax[blockIdx.x*32768 + bh*512 + n0 + tid] = fmaxf(pm[0][tid], pm[1][tid]);
    }
}

// ---------------- ctxT[e][m] = sum_n V[n][e]*pk[n][m], fp16, double-buffered -------
__global__ void __launch_bounds__(256, 2) ctx_mma(
    const float* __restrict__ uk, const __half* __restrict__ qkv16,
    const float* __restrict__ diag, __half* __restrict__ ctxT,
    float* __restrict__ ps)
{
    __shared__ __half VsT[2][96*40];     // [e][n]
    __shared__ __half PsT[2][64*40];     // [m][n]
    __shared__ float redc[256];
    int tid = threadIdx.x, lane = tid & 31, wid = tid >> 5;
    int wm = wid & 1, wn = wid >> 1;  // e split 2 (48), m split 4 (16)
    int m0 = blockIdx.x*64, bh = blockIdx.y;
    int b = bh >> 3, h = bh & 7;
    const __half* Vb = qkv16 + (size_t)(b*512)*2304 + 1536 + h*96;
    const float* Pb = uk + (size_t)(bh*512)*256 + m0;
    const float* dgk = diag + 32768 + bh*512;
    float kst = dec_f(g_kmax);
    int lq = lane >> 2, lr = lane & 3;

    int fn = tid >> 3;            // n within chunk (0..31)
    int fe = (tid & 7)*12;        // e start
    int fm = (tid & 7)*8;         // m start

    uint32_t vreg[6]; float preg[8]; float off = 0.f;
    auto loadRegs = [&](int c){
        const uint32_t* vp = (const uint32_t*)(Vb + (size_t)(c*32 + fn)*2304 + fe);
        #pragma unroll
        for (int j = 0; j < 6; j++) vreg[j] = vp[j];
        const float* pr = Pb + (size_t)(c*32 + fn)*256 + fm;
        float4 q0 = *(const float4*)pr, q1 = *(const float4*)(pr + 4);
        preg[0]=q0.x; preg[1]=q0.y; preg[2]=q0.z; preg[3]=q0.w;
        preg[4]=q1.x; preg[5]=q1.y; preg[6]=q1.z; preg[7]=q1.w;
        off = dgk[c*32 + fn] + kst;
    };
    auto storeSmem = [&](int buf){
        #pragma unroll
        for (int j = 0; j < 6; j++){
            __half2 hv = *reinterpret_cast<__half2*>(&vreg[j]);
            VsT[buf][(fe + 2*j)*40 + fn]     = __low2half(hv);
            VsT[buf][(fe + 2*j + 1)*40 + fn] = __high2half(hv);
        }
        #pragma unroll
        for (int j = 0; j < 8; j++)
            PsT[buf][(fm + j)*40 + fn] = phih(preg[j], off);
    };

    float acc[3][2][4];
    #pragma unroll
    for (int mt = 0; mt < 3; mt++)
        #pragma unroll
        for (int nt = 0; nt < 2; nt++)
            #pragma unroll
            for (int r = 0; r < 4; r++) acc[mt][nt][r] = 0.f;

    loadRegs(0);
    storeSmem(0);
    __syncthreads();

    int csm = tid & 63, csp = tid >> 6;
    float colsum = 0.f;
    int buf = 0;

    for (int c = 0; c < 16; c++){
        if (c < 15){ loadRegs(c + 1); storeSmem(buf ^ 1); }

        #pragma unroll
        for (int ks = 0; ks < 2; ks++){
            int kb = ks*16 + 2*lr;
            uint32_t a[3][4], bfr[2][2];
            int er = wm*48 + lq;
            #pragma unroll
            for (int mt = 0; mt < 3; mt++){
                const __half* p0 = &VsT[buf][(er + mt*16)*40 + kb];
                const __half* p1 = &VsT[buf][(er + mt*16 + 8)*40 + kb];
                a[mt][0] = LDH2(p0); a[mt][1] = LDH2(p1);
                a[mt][2] = LDH2(p0 + 8); a[mt][3] = LDH2(p1 + 8);
            }
            int bm = wn*16 + lq;
            #pragma unroll
            for (int nt = 0; nt < 2; nt++){
                const __half* p = &PsT[buf][(bm + nt*8)*40 + kb];
                bfr[nt][0] = LDH2(p); bfr[nt][1] = LDH2(p + 8);
            }
            #pragma unroll
            for (int mt = 0; mt < 3; mt++)
                #pragma unroll
                for (int nt = 0; nt < 2; nt++)
                    mma_f16(acc[mt][nt], a[mt], bfr[nt]);
        }
        {
            const __half* p = &PsT[buf][csm*40 + csp*8];
            float s = 0.f;
            #pragma unroll
            for (int j = 0; j < 8; j++) s += __half2float(p[j]);
            colsum += s;
        }
        __syncthreads();
        buf ^= 1;
    }

    redc[tid] = colsum;
    __syncthreads();
    if (tid < 64)
        ps[bh*256 + m0 + tid] = redc[tid] + redc[tid+64] + redc[tid+128] + redc[tid+192];

    #pragma unroll
    for (int mt = 0; mt < 3; mt++){
        int e = wm*48 + mt*16 + lq;
        int m = m0 + wn*16 + lr*2;
        __half* c0 = ctxT + ((size_t)bh*96 + e)*256;
        __half* c1 = ctxT + ((size_t)bh*96 + e + 8)*256;
        #pragma unroll
        for (int nt = 0; nt < 2; nt++){
            *(__half2*)(c0 + m + nt*8) = __floats2half2_rn(acc[mt][nt][0], acc[mt][nt][1]);
            *(__half2*)(c1 + m + nt*8) = __floats2half2_rn(acc[mt][nt][2], acc[mt][nt][3]);
        }
    }
}

// ---------------- attn = (phi(uq) @ ctxT^T)/den, rowmax from pqmax, den fused ------
#define ATT_A (128*SH)              // halfs per A buffer
#define ATT_B (96*SH)               // halfs per B buffer
#define ATT_SMEM ((2*ATT_A + 2*ATT_B)*2)   // 64512 bytes
__global__ void __launch_bounds__(256, 2) attn_out_mma(
    const float* __restrict__ uq, const __half* __restrict__ ctxT,
    const float* __restrict__ diagq, const float* __restrict__ ps,
    const float* __restrict__ pqmax, __half* __restrict__ attn16)
{
    extern __shared__ __half smh[];
    __half* Asb[2] = { smh, smh + ATT_A };
    __half* Bsb[2] = { smh + 2*ATT_A, smh + 2*ATT_A + ATT_B };
    __shared__ float denS[128];
    int tid = threadIdx.x, lane = tid & 31, wid = tid >> 5;
    int wm = wid & 3, wn = wid >> 2;  // n split 4 (32), e split 2 (48)
    int n0 = blockIdx.x*128, bh = blockIdx.y;
    int b = bh >> 3, h = bh & 7;
    const float* Ab = uq + ((size_t)bh*512 + n0)*256;
    const __half* Bb = ctxT + (size_t)bh*96*256;
    const float* psb = ps + bh*256;
    int lq = lane >> 2, lr = lane & 3;

    int fn = tid >> 1, fmg = (tid & 1)*32;
    int grow = bh*512 + n0 + fn;
    float offr = diagq[grow] + fmaxf(pqmax[grow], pqmax[32768 + grow]);
    float sden = 0.f;
    float areg[32];
    auto loadA = [&](int c){
        const float* p = Ab + (size_t)fn*256 + c*64 + fmg;
        #pragma unroll
        for (int j = 0; j < 8; j++){
            float4 q = *(const float4*)(p + j*4);
            areg[j*4+0]=q.x; areg[j*4+1]=q.y; areg[j*4+2]=q.z; areg[j*4+3]=q.w;
        }
    };
    auto storeA = [&](int buf, int c){
        __half* dst = Asb[buf] + fn*SH + fmg;
        const float* pp = psb + c*64 + fmg;
        #pragma unroll
        for (int j = 0; j < 16; j++){
            __half2 hv; hv.x = phih(areg[2*j], offr); hv.y = phih(areg[2*j+1], offr);
            *(__half2*)(dst + 2*j) = hv;
            sden += __half2float(hv.x)*pp[2*j] + __half2float(hv.y)*pp[2*j+1];
        }
    };
    auto issueB = [&](int c, int buf){
        uint32_t base = smem_u32(Bsb[buf]);
        #pragma unroll
        for (int i = 0; i < 3; i++){
            int p = tid + i*256; int r = p >> 3, cc = p & 7;
            CPA16(base + (uint32_t)(r*SH + cc*8)*2,
                  Bb + (size_t)r*256 + c*64 + cc*8);
        }
        asm volatile("cp.async.commit_group;");
    };

    float acc[2][6][4];
    #pragma unroll
    for (int mt = 0; mt < 2; mt++)
        #pragma unroll
        for (int nt = 0; nt < 6; nt++)
            #pragma unroll
            for (int r = 0; r < 4; r++) acc[mt][nt][r] = 0.f;

    issueB(0, 0); loadA(0); storeA(0, 0);
    asm volatile("cp.async.wait_group 0;" ::: "memory");
    __syncthreads();

    int buf = 0;
    for (int c = 0; c < 4; c++){
        if (c < 3){ issueB(c + 1, buf ^ 1); loadA(c + 1); }

        #pragma unroll
        for (int ks = 0; ks < 4; ks++){
            int kb = ks*16 + 2*lr;
            uint32_t a[2][4], bfr[6][2];
            int ar = wm*32 + lq;
            #pragma unroll
            for (int mt = 0; mt < 2; mt++){
                const __half* p0 = Asb[buf] + (size_t)(ar + mt*16)*SH + kb;
                const __half* p1 = Asb[buf] + (size_t)(ar + mt*16 + 8)*SH + kb;
                a[mt][0] = LDH2(p0); a[mt][1] = LDH2(p1);
                a[mt][2] = LDH2(p0 + 8); a[mt][3] = LDH2(p1 + 8);
            }
            int ec = wn*48 + lq;
            #pragma unroll
            for (int nt = 0; nt < 6; nt++){
                const __half* p = Bsb[buf] + (size_t)(ec + nt*8)*SH + kb;
                bfr[nt][0] = LDH2(p); bfr[nt][1] = LDH2(p + 8);
            }
            #pragma unroll
            for (int mt = 0; mt < 2; mt++)
                #pragma unroll
                for (int nt = 0; nt < 6; nt++)
                    mma_f16(acc[mt][nt], a[mt], bfr[nt]);
        }
        __syncthreads();
        if (c < 3){
            storeA(buf ^ 1, c + 1);
            asm volatile("cp.async.wait_group 0;" ::: "memory");
            __syncthreads();
            buf ^= 1;
        }
    }

    sden += __shfl_xor_sync(0xffffffffu, sden, 1);
    if ((tid & 1) == 0) denS[fn] = sden;
    __syncthreads();

    #pragma unroll
    for (int mt = 0; mt < 2; mt++){
        int nloc = wm*32 + mt*16 + lq;
        int n = n0 + nloc;
        float d0 = 1.f/denS[nloc];
        float d1 = 1.f/denS[nloc + 8];
        __half* o0 = attn16 + (size_t)(b*512 + n)*768 + h*96;
        __half* o1 = attn16 + (size_t)(b*512 + n + 8)*768 + h*96;
        int e = wn*48 + lr*2;
        #pragma unroll
        for (int nt = 0; nt < 6; nt++){
            *(__half2*)(o0 + e + nt*8) = __floats2half2_rn(acc[mt][nt][0]*d0, acc[mt][nt][1]*d0);
            *(__half2*)(o1 + e + nt*8) = __floats2half2_rn(acc[mt][nt][2]*d1, acc[mt][nt][3]*d1);
        }
    }
}

// ---------------- prep kernels ----------------
__global__ void transpose_w(const float* __restrict__ src, __half* __restrict__ dst,
                            int K, int N)
{
    __shared__ float t[32][33];
    int n0 = blockIdx.x*32, k0 = blockIdx.y*32;
    size_t off = (size_t)blockIdx.z * (size_t)K * N;
    src += off; dst += off;
    int tx = threadIdx.x & 31, ty = threadIdx.x >> 5;
    #pragma unroll
    for (int i = 0; i < 32; i += 8)
        t[ty+i][tx] = src[(size_t)(k0+ty+i)*N + n0+tx];
    __syncthreads();
    #pragma unroll
    for (int i = 0; i < 32; i += 8){
        int r = ty + i;
        if (tx < 16){
            __half2 hv = __floats2half2_rn(t[tx*2][r], t[tx*2+1][r]);
            *(__half2*)(dst + (size_t)(n0+r)*K + k0 + tx*2) = hv;
        }
    }
}

__global__ void copy_round(const float* __restrict__ src, __half* __restrict__ dst){
    int i = blockIdx.x*256 + threadIdx.x;
    dst[i] = __float2half_rn(src[i]);
}

__global__ void proj_prep(const float* __restrict__ proj, __half* __restrict__ ph){
    int i = blockIdx.x*256 + threadIdx.x;   // 24576
    ph[i] = __float2half_rn(proj[i]*0.31947155f);
}

__global__ void im2col_kernel(const float* __restrict__ mel, __half* __restrict__ dst){
    int idx = blockIdx.x*256 + threadIdx.x;
    int pg = idx >> 8, k = idx & 255;
    int b = pg >> 9, p = pg & 511;
    int oh = p >> 3, ow = p & 7;
    int i = k >> 4, j = k & 15;
    dst[idx] = __float2half_rn(mel[(size_t)b*131072 + (size_t)(oh*16 + i)*128 + ow*16 + j]);
}

// ---------------- layernorm: warp per row, fp16 out; resets g_kmax ----------------
__global__ void ln_kernel(const float* __restrict__ X, const float* __restrict__ sc,
                          const float* __restrict__ bb, __half* __restrict__ Y)
{
    int tid = threadIdx.x, lane = tid & 31, w = tid >> 5;
    if (blockIdx.x == 0 && tid == 0) g_kmax = 0u;
    int row = blockIdx.x*8 + w;
    const float* xr = X + (size_t)row*DMODEL;
    float v[24]; float sum = 0.f, sq = 0.f;
    #pragma unroll
    for (int i = 0; i < 24; i++){
        v[i] = xr[lane + 32*i];
        sum += v[i]; sq += v[i]*v[i];
    }
    sum = wsum(sum); sq = wsum(sq);
    float mean = sum*(1.f/768.f);
    float var  = sq*(1.f/768.f) - mean*mean;
    float rstd = rsqrtf(var + 1e-5f);
    __half* yr = Y + (size_t)row*DMODEL;
    #pragma unroll
    for (int i = 0; i < 24; i++){
        int d = lane + 32*i;
        yr[d] = __float2half_rn((v[i] - mean)*rstd*sc[d] + bb[d]);
    }
}

// ---------------- mask head ----------------
__global__ void mask_kernel(const float* __restrict__ X, const float* __restrict__ mw,
                            const float* __restrict__ mb, float* __restrict__ out)
{
    int row = blockIdx.x;
    int tid = threadIdx.x;
    int w = tid >> 5, lane = tid & 31;
    const float* xr = X + (size_t)row*768;
    float s = 0.f;
    for (int d = lane; d < 768; d += 32) s += xr[d]*mw[d*4 + w];
    s = wsum(s);
    if (lane == 0){
        float logit = s + mb[w];
        int b = row >> 9, n = row & 511;
        out[((size_t)b*4 + w)*512 + n] = 1.f/(1.f + expf(-logit));
    }
}

// ---------------- driver ----------------
extern "C" void kernel_launch(void* const* d_in, const int* in_sizes, int n_in,
                              void* d_out, int out_size)
{
    (void)in_sizes; (void)n_in; (void)out_size;
    const float* mel     = (const float*)d_in[0];
    const float* patch_w = (const float*)d_in[1];
    const float* patch_b = (const float*)d_in[2];
    const float* pos     = (const float*)d_in[3];
    const float* proj    = (const float*)d_in[4];
    const float* ln1_s   = (const float*)d_in[5];
    const float* ln1_b   = (const float*)d_in[6];
    const float* qkv_w   = (const float*)d_in[7];
    const float* qkv_b   = (const float*)d_in[8];
    const float* ao_w    = (const float*)d_in[9];
    const float* ao_b    = (const float*)d_in[10];
    const float* ln2_s   = (const float*)d_in[11];
    const float* ln2_b   = (const float*)d_in[12];
    const float* ff1_w   = (const float*)d_in[13];
    const float* ff1_b   = (const float*)d_in[14];
    const float* ff2_w   = (const float*)d_in[15];
    const float* ff2_b   = (const float*)d_in[16];
    const float* mask_w  = (const float*)d_in[17];
    const float* mask_b  = (const float*)d_in[18];
    float* out = (float*)d_out;

    float *x, *uq, *uk, *diag, *ps, *pqm;
    __half *lnb, *qkv, *ffb, *ctxb, *attn, *im2, *pwT, *projh;
    __half *wtq, *wtao, *wtf1, *wtf2;
    cudaGetSymbolAddress((void**)&x,    g_x);
    cudaGetSymbolAddress((void**)&lnb,  g_lnbuf);
    cudaGetSymbolAddress((void**)&qkv,  g_qkv);
    cudaGetSymbolAddress((void**)&ffb,  g_ffbuf);
    cudaGetSymbolAddress((void**)&uq,   g_uq);
    cudaGetSymbolAddress((void**)&uk,   g_uk);
    cudaGetSymbolAddress((void**)&ctxb, g_ctxb);
    cudaGetSymbolAddress((void**)&attn, g_attn);
    cudaGetSymbolAddress((void**)&diag, g_diag);
    cudaGetSymbolAddress((void**)&ps,   g_pksum);
    cudaGetSymbolAddress((void**)&pqm,  g_pqmax);
    cudaGetSymbolAddress((void**)&im2,  g_im2col);
    cudaGetSymbolAddress((void**)&pwT,  g_pwT);
    cudaGetSymbolAddress((void**)&projh,g_projh);
    cudaGetSymbolAddress((void**)&wtq,  g_wt_qkv);
    cudaGetSymbolAddress((void**)&wtao, g_wt_ao);
    cudaGetSymbolAddress((void**)&wtf1, g_wt_ff1);
    cudaGetSymbolAddress((void**)&wtf2, g_wt_ff2);

    cudaFuncSetAttribute(gemm_tc, cudaFuncAttributeMaxDynamicSharedMemorySize, GEMM_SMEM);
    cudaFuncSetAttribute(phi_u_mma, cudaFuncAttributeMaxDynamicSharedMemorySize, PHI_SMEM);
    cudaFuncSetAttribute(attn_out_mma, cudaFuncAttributeMaxDynamicSharedMemorySize, ATT_SMEM);

    // weight prep (fp16 [N][K])
    copy_round<<<768, 256>>>(patch_w, pwT);
    proj_prep<<<96, 256>>>(proj, projh);
    transpose_w<<<dim3(72, 24, 6), 256>>>(qkv_w, wtq, 768, 2304);
    transpose_w<<<dim3(24, 24, 6), 256>>>(ao_w,  wtao, 768, 768);
    transpose_w<<<dim3(96, 24, 6), 256>>>(ff1_w, wtf1, 768, 3072);
    transpose_w<<<dim3(24, 96, 6), 256>>>(ff2_w, wtf2, 3072, 768);

    // patch embed
    im2col_kernel<<<4096, 256>>>(mel, im2);
    gemm_tc<<<dim3(6, 32), 128, GEMM_SMEM>>>(im2, pwT, patch_b, x, 256, 768, 3, pos);

    for (int l = 0; l < NDEPTH; l++){
        ln_kernel<<<512, 256>>>(x, ln1_s + l*768, ln1_b + l*768, lnb);
        gemm_tc<<<dim3(18, 32), 128, GEMM_SMEM>>>(
            lnb, wtq + (size_t)l*2304*768, qkv_b + l*2304, (float*)qkv, 768, 2304, 0, 0);
        phi_u_mma<<<dim3(2, 4, 128), 256, PHI_SMEM>>>(qkv, projh, uq, uk, diag, pqm);
        ctx_mma<<<dim3(4, 64), 256>>>(uk, qkv, diag, ctxb, ps);
        attn_out_mma<<<dim3(4, 64), 256, ATT_SMEM>>>(uq, ctxb, diag, ps, pqm, attn);
        gemm_tc<<<dim3(6, 32), 128, GEMM_SMEM>>>(
            attn, wtao + (size_t)l*768*768, ao_b + l*768, x, 768, 768, 2, 0);
        ln_kernel<<<512, 256>>>(x, ln2_s + l*768, ln2_b + l*768, lnb);
        gemm_tc<<<dim3(24, 32), 128, GEMM_SMEM>>>(
            lnb, wtf1 + (size_t)l*768*3072, ff1_b + l*3072, (float*)ffb, 768, 3072, 1, 0);
        gemm_tc<<<dim3(6, 32), 128, GEMM_SMEM>>>(
            ffb, wtf2 + (size_t)l*3072*768, ff2_b + l*768, x, 3072, 768, 2, 0);
    }

    mask_kernel<<<4096, 128>>>(x, mask_w, mask_b, out);
}